// round 1
// baseline (speedup 1.0000x reference)
#include <cuda_runtime.h>
#include <math.h>

// Problem constants
#define Bq 4
#define Hh 8
#define Ss 2048
#define Dd 128
#define QKV_ELEMS (Bq*Hh*Ss*Dd)   // 8,388,608 floats = 32 MB each

#define SCALE 0.0883883476483184406f   // 1/sqrt(128)

// Scratch for projected Q (pre-scaled), K, V in [B,H,S,D] layout
__device__ float g_Q[QKV_ELEMS];
__device__ float g_K[QKV_ELEMS];
__device__ float g_V[QKV_ELEMS];

#define TS 132   // smem row stride (floats) for 128-wide tiles (16B-aligned, bank-friendly)
#define ASTR 68  // smem row stride for the A tile (128 x 64)

// Copy a [rows x 128] fp32 tile (gmem row stride = 128 floats) into smem with stride TS.
__device__ __forceinline__ void load_tile128(float* dst, const float* __restrict__ src, int rows) {
    for (int idx = threadIdx.x; idx < rows * 32; idx += 256) {
        int r  = idx >> 5;
        int c4 = (idx & 31) * 4;
        float4 v = *reinterpret_cast<const float4*>(src + r * 128 + c4);
        float* d = dst + r * TS + c4;
        d[0] = v.x; d[1] = v.y; d[2] = v.z; d[3] = v.w;
    }
}

// ---------------------------------------------------------------------------
// Kernel 1: QKV projection.  out[b,h,s,d] = sum_e x[b,s,e] * W[h*128+d, e]
// grid = (H=8, M/128=64, 3 mats), block = 256 threads, 128x128 tile, K=128.
// Q output is pre-scaled by 1/sqrt(D).
// ---------------------------------------------------------------------------
__global__ __launch_bounds__(256, 1)
void proj_kernel(const float* __restrict__ x,
                 const float* __restrict__ Wq,
                 const float* __restrict__ Wk,
                 const float* __restrict__ Wv)
{
    extern __shared__ float sm[];
    float* Xs = sm;              // [128][TS]
    float* Ws = sm + 128 * TS;   // [128][TS]

    const int which = blockIdx.z;
    const float* W = (which == 0) ? Wq : (which == 1) ? Wk : Wv;
    float* outg    = (which == 0) ? g_Q : (which == 1) ? g_K : g_V;

    const int m0 = blockIdx.y * 128;   // token-tile base (m = b*2048 + s)
    const int h  = blockIdx.x;         // head = n-tile (BN = 128 = D)

    load_tile128(Xs, x + (size_t)m0 * 128, 128);
    load_tile128(Ws, W + (size_t)h * 128 * 128, 128);
    __syncthreads();

    const int tx = threadIdx.x & 15;
    const int ty = threadIdx.x >> 4;

    float acc[8][8];
#pragma unroll
    for (int i = 0; i < 8; i++)
#pragma unroll
        for (int j = 0; j < 8; j++) acc[i][j] = 0.f;

    for (int k = 0; k < 128; k += 4) {
        float4 a4[8], b4[8];
#pragma unroll
        for (int i = 0; i < 8; i++)
            a4[i] = *reinterpret_cast<const float4*>(Xs + (ty + 16 * i) * TS + k);
#pragma unroll
        for (int j = 0; j < 8; j++)
            b4[j] = *reinterpret_cast<const float4*>(Ws + (tx + 16 * j) * TS + k);
#pragma unroll
        for (int i = 0; i < 8; i++)
#pragma unroll
            for (int j = 0; j < 8; j++) {
                acc[i][j] += a4[i].x * b4[j].x;
                acc[i][j] += a4[i].y * b4[j].y;
                acc[i][j] += a4[i].z * b4[j].z;
                acc[i][j] += a4[i].w * b4[j].w;
            }
    }

    const float mul = (which == 0) ? SCALE : 1.0f;
#pragma unroll
    for (int i = 0; i < 8; i++) {
        int m = m0 + ty + 16 * i;
        int b = m >> 11;
        int s = m & 2047;
        float* orow = outg + (((size_t)(b * Hh + h)) * Ss + s) * Dd;
#pragma unroll
        for (int j = 0; j < 8; j++)
            orow[tx + 16 * j] = acc[i][j] * mul;
    }
}

// ---------------------------------------------------------------------------
// Kernel 2: fused attention per (b,h): Z = softmax_d( (Q K^T) V ).
// grid = (S/128=16, B*H=32), block = 256 threads.
// Each block: 128 Q rows, loops over 2048 K/V rows in tiles of 64.
//   phase 1: A[128][64] = Q_tile . K_tile^T   (staged to smem)
//   phase 2: Z[128][128] += A . V_tile        (64 fp32 accums / thread)
// Epilogue: softmax over the 128 head-dim columns via 16-lane shuffles.
// ---------------------------------------------------------------------------
__global__ __launch_bounds__(256, 1)
void attn_kernel(float* __restrict__ out)
{
    extern __shared__ float sm[];
    float* Qs = sm;                     // [128][TS]
    float* Ks = Qs + 128 * TS;          // [64][TS]
    float* Vs = Ks + 64 * TS;           // [64][TS]
    float* As = Vs + 64 * TS;           // [128][ASTR]

    const int bh = blockIdx.y;
    const int s0 = blockIdx.x * 128;

    const float* Qg = g_Q + ((size_t)bh * Ss + s0) * Dd;
    const float* Kg = g_K + (size_t)bh * Ss * Dd;
    const float* Vg = g_V + (size_t)bh * Ss * Dd;

    load_tile128(Qs, Qg, 128);

    const int tx = threadIdx.x & 15;
    const int ty = threadIdx.x >> 4;

    float z[8][8];
#pragma unroll
    for (int i = 0; i < 8; i++)
#pragma unroll
        for (int j = 0; j < 8; j++) z[i][j] = 0.f;

    for (int kt = 0; kt < Ss; kt += 64) {
        __syncthreads();   // prev phase2 done with Vs/As; also covers initial Qs load
        load_tile128(Ks, Kg + (size_t)kt * Dd, 64);
        load_tile128(Vs, Vg + (size_t)kt * Dd, 64);
        __syncthreads();

        // ---- phase 1: A = Q . K^T (Q pre-scaled) ----
        float a[8][4];
#pragma unroll
        for (int i = 0; i < 8; i++)
#pragma unroll
            for (int j = 0; j < 4; j++) a[i][j] = 0.f;

        for (int k = 0; k < 128; k += 4) {
            float4 q4[8], k4[4];
#pragma unroll
            for (int i = 0; i < 8; i++)
                q4[i] = *reinterpret_cast<const float4*>(Qs + (ty + 16 * i) * TS + k);
#pragma unroll
            for (int j = 0; j < 4; j++)
                k4[j] = *reinterpret_cast<const float4*>(Ks + (tx + 16 * j) * TS + k);
#pragma unroll
            for (int i = 0; i < 8; i++)
#pragma unroll
                for (int j = 0; j < 4; j++) {
                    a[i][j] += q4[i].x * k4[j].x;
                    a[i][j] += q4[i].y * k4[j].y;
                    a[i][j] += q4[i].z * k4[j].z;
                    a[i][j] += q4[i].w * k4[j].w;
                }
        }
#pragma unroll
        for (int i = 0; i < 8; i++)
#pragma unroll
            for (int j = 0; j < 4; j++)
                As[(ty + 16 * i) * ASTR + (tx + 16 * j)] = a[i][j];
        __syncthreads();

        // ---- phase 2: Z += A . V ----
        for (int t = 0; t < 64; t += 4) {
            float4 ar[8];
#pragma unroll
            for (int i = 0; i < 8; i++)
                ar[i] = *reinterpret_cast<const float4*>(As + (ty + 16 * i) * ASTR + t);
#pragma unroll
            for (int tt = 0; tt < 4; tt++) {
                const float* vrow = Vs + (t + tt) * TS + tx * 8;
                float4 va = *reinterpret_cast<const float4*>(vrow);
                float4 vb = *reinterpret_cast<const float4*>(vrow + 4);
#pragma unroll
                for (int i = 0; i < 8; i++) {
                    float av = (tt == 0) ? ar[i].x : (tt == 1) ? ar[i].y
                             : (tt == 2) ? ar[i].z : ar[i].w;
                    z[i][0] += av * va.x;  z[i][1] += av * va.y;
                    z[i][2] += av * va.z;  z[i][3] += av * va.w;
                    z[i][4] += av * vb.x;  z[i][5] += av * vb.y;
                    z[i][6] += av * vb.z;  z[i][7] += av * vb.w;
                }
            }
        }
    }

    // ---- epilogue: softmax over the 128 columns (head dim) of each row ----
#pragma unroll
    for (int i = 0; i < 8; i++) {
        float m = z[i][0];
#pragma unroll
        for (int j = 1; j < 8; j++) m = fmaxf(m, z[i][j]);
#pragma unroll
        for (int o = 8; o; o >>= 1)
            m = fmaxf(m, __shfl_xor_sync(0xffffffffu, m, o));

        float e[8];
        float ssum = 0.f;
#pragma unroll
        for (int j = 0; j < 8; j++) { e[j] = expf(z[i][j] - m); ssum += e[j]; }
#pragma unroll
        for (int o = 8; o; o >>= 1)
            ssum += __shfl_xor_sync(0xffffffffu, ssum, o);

        float inv = 1.0f / ssum;
        int srow = s0 + ty + 16 * i;
        float* orow = out + ((size_t)bh * Ss + srow) * Dd + tx * 8;
        float4 o0 = make_float4(e[0] * inv, e[1] * inv, e[2] * inv, e[3] * inv);
        float4 o1 = make_float4(e[4] * inv, e[5] * inv, e[6] * inv, e[7] * inv);
        *reinterpret_cast<float4*>(orow)     = o0;
        *reinterpret_cast<float4*>(orow + 4) = o1;
    }
}

// ---------------------------------------------------------------------------

#define PROJ_SMEM (2 * 128 * TS * (int)sizeof(float))                       // 135168 B
#define ATTN_SMEM ((128 * TS + 2 * 64 * TS + 128 * ASTR) * (int)sizeof(float))  // 169984 B

extern "C" void kernel_launch(void* const* d_in, const int* in_sizes, int n_in,
                              void* d_out, int out_size)
{
    (void)in_sizes; (void)n_in; (void)out_size;
    const float* x  = (const float*)d_in[0];
    const float* Wq = (const float*)d_in[1];
    const float* Wk = (const float*)d_in[2];
    const float* Wv = (const float*)d_in[3];
    float* out = (float*)d_out;

    cudaFuncSetAttribute(proj_kernel, cudaFuncAttributeMaxDynamicSharedMemorySize, PROJ_SMEM);
    cudaFuncSetAttribute(attn_kernel, cudaFuncAttributeMaxDynamicSharedMemorySize, ATTN_SMEM);

    proj_kernel<<<dim3(Hh, (Bq * Ss) / 128, 3), 256, PROJ_SMEM>>>(x, Wq, Wk, Wv);
    attn_kernel<<<dim3(Ss / 128, Bq * Hh), 256, ATTN_SMEM>>>(out);
}

// round 3
// speedup vs baseline: 1.8609x; 1.8609x over previous
#include <cuda_runtime.h>
#include <cuda_bf16.h>
#include <math.h>
#include <stdint.h>

// Problem constants
#define Bq 4
#define Hh 8
#define Ss 2048
#define Dd 128
#define QKV_ELEMS (Bq*Hh*Ss*Dd)
#define SCALE 0.0883883476483184406f   // 1/sqrt(128)

__device__ float g_Q[QKV_ELEMS];
__device__ float g_K[QKV_ELEMS];
__device__ float g_V[QKV_ELEMS];

// ===========================================================================
// Kernel 1: QKV projection (fp32 CUDA cores — known correct, ~190us)
// ===========================================================================
#define TS 132

__device__ __forceinline__ void load_tile128(float* dst, const float* __restrict__ src, int rows) {
    for (int idx = threadIdx.x; idx < rows * 32; idx += 256) {
        int r  = idx >> 5;
        int c4 = (idx & 31) * 4;
        float4 v = *reinterpret_cast<const float4*>(src + r * 128 + c4);
        float* d = dst + r * TS + c4;
        d[0] = v.x; d[1] = v.y; d[2] = v.z; d[3] = v.w;
    }
}

__global__ __launch_bounds__(256, 1)
void proj_kernel(const float* __restrict__ x,
                 const float* __restrict__ Wq,
                 const float* __restrict__ Wk,
                 const float* __restrict__ Wv)
{
    extern __shared__ float smf[];
    float* Xs = smf;
    float* Ws = smf + 128 * TS;

    const int which = blockIdx.z;
    const float* W = (which == 0) ? Wq : (which == 1) ? Wk : Wv;
    float* outg    = (which == 0) ? g_Q : (which == 1) ? g_K : g_V;

    const int m0 = blockIdx.y * 128;
    const int h  = blockIdx.x;

    load_tile128(Xs, x + (size_t)m0 * 128, 128);
    load_tile128(Ws, W + (size_t)h * 128 * 128, 128);
    __syncthreads();

    const int tx = threadIdx.x & 15;
    const int ty = threadIdx.x >> 4;

    float acc[8][8];
#pragma unroll
    for (int i = 0; i < 8; i++)
#pragma unroll
        for (int j = 0; j < 8; j++) acc[i][j] = 0.f;

    for (int k = 0; k < 128; k += 4) {
        float4 a4[8], b4[8];
#pragma unroll
        for (int i = 0; i < 8; i++)
            a4[i] = *reinterpret_cast<const float4*>(Xs + (ty + 16 * i) * TS + k);
#pragma unroll
        for (int j = 0; j < 8; j++)
            b4[j] = *reinterpret_cast<const float4*>(Ws + (tx + 16 * j) * TS + k);
#pragma unroll
        for (int i = 0; i < 8; i++)
#pragma unroll
            for (int j = 0; j < 8; j++) {
                acc[i][j] += a4[i].x * b4[j].x;
                acc[i][j] += a4[i].y * b4[j].y;
                acc[i][j] += a4[i].z * b4[j].z;
                acc[i][j] += a4[i].w * b4[j].w;
            }
    }

    const float mul = (which == 0) ? SCALE : 1.0f;
#pragma unroll
    for (int i = 0; i < 8; i++) {
        int m = m0 + ty + 16 * i;
        int b = m >> 11;
        int s = m & 2047;
        float* orow = outg + (((size_t)(b * Hh + h)) * Ss + s) * Dd;
#pragma unroll
        for (int j = 0; j < 8; j++)
            orow[tx + 16 * j] = acc[i][j] * mul;
    }
}

// ===========================================================================
// mma.sync / ldmatrix helpers (portable tensor-core path; no 'a' features)
// ===========================================================================
__device__ __forceinline__ uint32_t swz(uint32_t o) {
    // 256-byte rows of bf16 (128 cols); XOR 16B-chunk index with row%8
    return o ^ (((o >> 8) & 7) << 4);
}

// pack two f32 -> bf16x2 (lo element in low half)
__device__ __forceinline__ uint32_t pk(float e_lo, float e_hi) {
    uint32_t r;
    asm("cvt.rn.bf16x2.f32 %0, %1, %2;" : "=r"(r) : "f"(e_hi), "f"(e_lo));
    return r;
}

// split f32 into bf16-representable hi (as f32) and residual lo (as f32)
__device__ __forceinline__ void sp(float x, float& hf, float& lf) {
    __nv_bfloat16 hb = __float2bfloat16(x);
    hf = __bfloat162float(hb);
    lf = x - hf;
}

__device__ __forceinline__ void ldsm4(uint32_t addr, uint32_t r[4]) {
    asm volatile("ldmatrix.sync.aligned.m8n8.x4.shared.b16 {%0,%1,%2,%3}, [%4];"
                 : "=r"(r[0]), "=r"(r[1]), "=r"(r[2]), "=r"(r[3]) : "r"(addr));
}
__device__ __forceinline__ void ldsm4t(uint32_t addr, uint32_t r[4]) {
    asm volatile("ldmatrix.sync.aligned.m8n8.x4.trans.shared.b16 {%0,%1,%2,%3}, [%4];"
                 : "=r"(r[0]), "=r"(r[1]), "=r"(r[2]), "=r"(r[3]) : "r"(addr));
}

__device__ __forceinline__ void mma16816(float c[4], const uint32_t a[4],
                                         uint32_t b0, uint32_t b1) {
    asm volatile(
        "mma.sync.aligned.m16n8k16.row.col.f32.bf16.bf16.f32 "
        "{%0,%1,%2,%3}, {%4,%5,%6,%7}, {%8,%9}, {%0,%1,%2,%3};"
        : "+f"(c[0]), "+f"(c[1]), "+f"(c[2]), "+f"(c[3])
        : "r"(a[0]), "r"(a[1]), "r"(a[2]), "r"(a[3]), "r"(b0), "r"(b1));
}

// ===========================================================================
// Kernel 2: tensor-core attention via mma.sync, bf16 hi/lo split (3 MMAs).
// Per block: (bh, 128 q rows), 8 warps, warp w owns rows w*16..w*16+15.
// ===========================================================================
#define QHI 0
#define QLO 32768
#define KHI 65536
#define KLO 81920
#define VHI 98304
#define VLO 114688
#define ATTN_SMEM 131072

// Stage a [rows x 128] fp32 tile into swizzled bf16 hi/lo smem tiles.
// nseg = rows*16 (each segment = 8 consecutive floats = one 16B bf16 chunk).
__device__ __forceinline__ void stage_tile(char* sm, int offH, int offL,
                                           const float* __restrict__ g, int nseg) {
    for (int idx = threadIdx.x; idx < nseg; idx += 256) {
        int r = idx >> 4, s = idx & 15;
        const float* p = g + r * 128 + s * 8;
        float4 u = *reinterpret_cast<const float4*>(p);
        float4 w = *reinterpret_cast<const float4*>(p + 4);
        float f[8] = {u.x, u.y, u.z, u.w, w.x, w.y, w.z, w.w};
        uint32_t hp[4], lp[4];
#pragma unroll
        for (int e = 0; e < 4; e++) {
            float h0, l0, h1, l1;
            sp(f[2 * e], h0, l0);
            sp(f[2 * e + 1], h1, l1);
            hp[e] = pk(h0, h1);
            lp[e] = pk(l0, l1);
        }
        uint32_t o = swz((uint32_t)(r * 256 + s * 16));
        *reinterpret_cast<uint4*>(sm + offH + o) = make_uint4(hp[0], hp[1], hp[2], hp[3]);
        *reinterpret_cast<uint4*>(sm + offL + o) = make_uint4(lp[0], lp[1], lp[2], lp[3]);
    }
}

__global__ __launch_bounds__(256, 1)
void attn_mma(float* __restrict__ out)
{
    extern __shared__ char sm[];
    const uint32_t sb = (uint32_t)__cvta_generic_to_shared(sm);
    const int tid  = threadIdx.x;
    const int wid  = tid >> 5;
    const int lane = tid & 31;
    const int bh = blockIdx.y;
    const int q0 = blockIdx.x * 128;
    const int m0w = wid * 16;   // warp's q-row base within the tile

    const float* Qg = g_Q + ((size_t)bh * Ss + q0) * Dd;
    const float* Kg = g_K + (size_t)bh * Ss * Dd;
    const float* Vg = g_V + (size_t)bh * Ss * Dd;

    stage_tile(sm, QHI, QLO, Qg, 2048);

    // ldmatrix lane-address components (constant per thread)
    const int l15 = lane & 15;
    const int lhi8 = (lane >> 4) << 3;          // 0 or 8 (second address-halves)
    const int bl_row = ((lane >> 4) << 3) + (lane & 7);  // for GEMM1 B x4 (j-pairs)
    const int bl_col = ((lane >> 3) & 1) << 3;

    float zacc[16][4];
#pragma unroll
    for (int j = 0; j < 16; j++)
#pragma unroll
        for (int e = 0; e < 4; e++) zacc[j][e] = 0.f;

    for (int kt = 0; kt < 32; kt++) {
        __syncthreads();   // everyone done reading K/V of previous tile
        stage_tile(sm, KHI, KLO, Kg + (size_t)kt * 64 * 128, 1024);
        stage_tile(sm, VHI, VLO, Vg + (size_t)kt * 64 * 128, 1024);
        __syncthreads();

        // ---- GEMM1: S[16(warp rows), 64] = Q . K^T ----
        float sacc[8][4];
#pragma unroll
        for (int j = 0; j < 8; j++)
#pragma unroll
            for (int e = 0; e < 4; e++) sacc[j][e] = 0.f;

#pragma unroll
        for (int kc = 0; kc < 8; kc++) {
            uint32_t ah[4], al[4];
            {
                uint32_t o = swz((uint32_t)((m0w + l15) * 256 + (kc * 16 + lhi8) * 2));
                ldsm4(sb + QHI + o, ah);
                ldsm4(sb + QLO + o, al);
            }
#pragma unroll
            for (int jj = 0; jj < 4; jj++) {
                uint32_t bh4[4], bl4[4];
                uint32_t o = swz((uint32_t)((jj * 16 + bl_row) * 256 + (kc * 16 + bl_col) * 2));
                ldsm4(sb + KHI + o, bh4);
                ldsm4(sb + KLO + o, bl4);
                // j = 2*jj : B = {bh4[0], bh4[1]} ; j = 2*jj+1 : {bh4[2], bh4[3]}
                mma16816(sacc[2 * jj],     ah, bh4[0], bh4[1]);
                mma16816(sacc[2 * jj],     ah, bl4[0], bl4[1]);
                mma16816(sacc[2 * jj],     al, bh4[0], bh4[1]);
                mma16816(sacc[2 * jj + 1], ah, bh4[2], bh4[3]);
                mma16816(sacc[2 * jj + 1], ah, bl4[2], bl4[3]);
                mma16816(sacc[2 * jj + 1], al, bh4[2], bh4[3]);
            }
        }

        // ---- GEMM2: Z[16,128] += S . V  (S passes through registers) ----
#pragma unroll
        for (int p = 0; p < 4; p++) {
            // Convert S accum (n-tiles 2p, 2p+1) into A fragments (hi & lo)
            uint32_t ah[4], al[4];
            {
                float h0, l0, h1, l1;
                sp(sacc[2 * p][0], h0, l0); sp(sacc[2 * p][1], h1, l1);
                ah[0] = pk(h0, h1); al[0] = pk(l0, l1);
                sp(sacc[2 * p][2], h0, l0); sp(sacc[2 * p][3], h1, l1);
                ah[1] = pk(h0, h1); al[1] = pk(l0, l1);
                sp(sacc[2 * p + 1][0], h0, l0); sp(sacc[2 * p + 1][1], h1, l1);
                ah[2] = pk(h0, h1); al[2] = pk(l0, l1);
                sp(sacc[2 * p + 1][2], h0, l0); sp(sacc[2 * p + 1][3], h1, l1);
                ah[3] = pk(h0, h1); al[3] = pk(l0, l1);
            }
#pragma unroll
            for (int np = 0; np < 8; np++) {
                uint32_t bh4[4], bl4[4];
                uint32_t o = swz((uint32_t)((p * 16 + l15) * 256 + (np * 16 + lhi8) * 2));
                ldsm4t(sb + VHI + o, bh4);
                ldsm4t(sb + VLO + o, bl4);
                mma16816(zacc[2 * np],     ah, bh4[0], bh4[1]);
                mma16816(zacc[2 * np],     ah, bl4[0], bl4[1]);
                mma16816(zacc[2 * np],     al, bh4[0], bh4[1]);
                mma16816(zacc[2 * np + 1], ah, bh4[2], bh4[3]);
                mma16816(zacc[2 * np + 1], ah, bl4[2], bl4[3]);
                mma16816(zacc[2 * np + 1], al, bh4[2], bh4[3]);
            }
        }
    }

    // ---- epilogue: softmax over head dim (128 cols), rows live in quads ----
    const int g = lane >> 2;
    const int t = lane & 3;

#pragma unroll
    for (int half = 0; half < 2; half++) {
        // half 0: row m0w+g (regs 0,1); half 1: row m0w+g+8 (regs 2,3)
        float e[32];
#pragma unroll
        for (int j = 0; j < 16; j++) {
            e[2 * j]     = zacc[j][half * 2];
            e[2 * j + 1] = zacc[j][half * 2 + 1];
        }
        float m = e[0];
#pragma unroll
        for (int c = 1; c < 32; c++) m = fmaxf(m, e[c]);
        m = fmaxf(m, __shfl_xor_sync(0xffffffffu, m, 1));
        m = fmaxf(m, __shfl_xor_sync(0xffffffffu, m, 2));

        float ssum = 0.f;
#pragma unroll
        for (int c = 0; c < 32; c++) { e[c] = expf(e[c] - m); ssum += e[c]; }
        ssum += __shfl_xor_sync(0xffffffffu, ssum, 1);
        ssum += __shfl_xor_sync(0xffffffffu, ssum, 2);
        float inv = 1.0f / ssum;

        int row = q0 + m0w + g + half * 8;
        float* orow = out + ((size_t)bh * Ss + row) * Dd;
#pragma unroll
        for (int j = 0; j < 16; j++) {
            float2 o2 = make_float2(e[2 * j] * inv, e[2 * j + 1] * inv);
            *reinterpret_cast<float2*>(orow + j * 8 + 2 * t) = o2;
        }
    }
}

// ===========================================================================

#define PROJ_SMEM (2 * 128 * TS * (int)sizeof(float))

extern "C" void kernel_launch(void* const* d_in, const int* in_sizes, int n_in,
                              void* d_out, int out_size)
{
    (void)in_sizes; (void)n_in; (void)out_size;
    const float* x  = (const float*)d_in[0];
    const float* Wq = (const float*)d_in[1];
    const float* Wk = (const float*)d_in[2];
    const float* Wv = (const float*)d_in[3];
    float* out = (float*)d_out;

    cudaFuncSetAttribute(proj_kernel, cudaFuncAttributeMaxDynamicSharedMemorySize, PROJ_SMEM);
    cudaFuncSetAttribute(attn_mma, cudaFuncAttributeMaxDynamicSharedMemorySize, ATTN_SMEM);

    proj_kernel<<<dim3(Hh, (Bq * Ss) / 128, 3), 256, PROJ_SMEM>>>(x, Wq, Wk, Wv);
    attn_mma<<<dim3(Ss / 128, Bq * Hh), 256, ATTN_SMEM>>>(out);
}

// round 4
// speedup vs baseline: 2.9956x; 1.6098x over previous
#include <cuda_runtime.h>
#include <cuda_bf16.h>
#include <math.h>
#include <stdint.h>

// Problem constants
#define Bq 4
#define Hh 8
#define Ss 2048
#define Dd 128
#define QKV_ELEMS (Bq*Hh*Ss*Dd)
#define SCALE 0.0883883476483184406f   // 1/sqrt(128)

// Pre-split bf16 hi/lo QKV (written by proj, consumed by attn)
__device__ __nv_bfloat16 g_Qhi[QKV_ELEMS];
__device__ __nv_bfloat16 g_Qlo[QKV_ELEMS];
__device__ __nv_bfloat16 g_Khi[QKV_ELEMS];
__device__ __nv_bfloat16 g_Klo[QKV_ELEMS];
__device__ __nv_bfloat16 g_Vhi[QKV_ELEMS];
__device__ __nv_bfloat16 g_Vlo[QKV_ELEMS];

// ===========================================================================
// Kernel 1: QKV projection (fp32 CUDA cores), writes hi/lo bf16 split.
// ===========================================================================
#define TS 132

__device__ __forceinline__ void load_tile128(float* dst, const float* __restrict__ src, int rows) {
    for (int idx = threadIdx.x; idx < rows * 32; idx += 256) {
        int r  = idx >> 5;
        int c4 = (idx & 31) * 4;
        float4 v = *reinterpret_cast<const float4*>(src + r * 128 + c4);
        float* d = dst + r * TS + c4;
        d[0] = v.x; d[1] = v.y; d[2] = v.z; d[3] = v.w;
    }
}

__global__ __launch_bounds__(256, 1)
void proj_kernel(const float* __restrict__ x,
                 const float* __restrict__ Wq,
                 const float* __restrict__ Wk,
                 const float* __restrict__ Wv)
{
    extern __shared__ float smf[];
    float* Xs = smf;
    float* Ws = smf + 128 * TS;

    const int which = blockIdx.z;
    const float* W = (which == 0) ? Wq : (which == 1) ? Wk : Wv;
    __nv_bfloat16* Ohi = (which == 0) ? g_Qhi : (which == 1) ? g_Khi : g_Vhi;
    __nv_bfloat16* Olo = (which == 0) ? g_Qlo : (which == 1) ? g_Klo : g_Vlo;

    const int m0 = blockIdx.y * 128;
    const int h  = blockIdx.x;

    load_tile128(Xs, x + (size_t)m0 * 128, 128);
    load_tile128(Ws, W + (size_t)h * 128 * 128, 128);
    __syncthreads();

    const int tx = threadIdx.x & 15;
    const int ty = threadIdx.x >> 4;

    float acc[8][8];
#pragma unroll
    for (int i = 0; i < 8; i++)
#pragma unroll
        for (int j = 0; j < 8; j++) acc[i][j] = 0.f;

    for (int k = 0; k < 128; k += 4) {
        float4 a4[8], b4[8];
#pragma unroll
        for (int i = 0; i < 8; i++)
            a4[i] = *reinterpret_cast<const float4*>(Xs + (ty + 16 * i) * TS + k);
#pragma unroll
        for (int j = 0; j < 8; j++)
            b4[j] = *reinterpret_cast<const float4*>(Ws + (tx + 16 * j) * TS + k);
#pragma unroll
        for (int i = 0; i < 8; i++)
#pragma unroll
            for (int j = 0; j < 8; j++) {
                acc[i][j] += a4[i].x * b4[j].x;
                acc[i][j] += a4[i].y * b4[j].y;
                acc[i][j] += a4[i].z * b4[j].z;
                acc[i][j] += a4[i].w * b4[j].w;
            }
    }

    const float mul = (which == 0) ? SCALE : 1.0f;
#pragma unroll
    for (int i = 0; i < 8; i++) {
        int m = m0 + ty + 16 * i;
        int b = m >> 11;
        int s = m & 2047;
        size_t rbase = (((size_t)(b * Hh + h)) * Ss + s) * Dd;
#pragma unroll
        for (int j = 0; j < 8; j++) {
            float v = acc[i][j] * mul;
            __nv_bfloat16 hb = __float2bfloat16(v);
            float lo = v - __bfloat162float(hb);
            Ohi[rbase + tx + 16 * j] = hb;
            Olo[rbase + tx + 16 * j] = __float2bfloat16(lo);
        }
    }
}

// ===========================================================================
// mma.sync / ldmatrix / cp.async helpers (portable; no sm_103a-only features)
// ===========================================================================
__device__ __forceinline__ uint32_t swz(uint32_t o) {
    // 256-byte rows of bf16 (128 cols); XOR 16B-chunk index with row%8
    return o ^ (((o >> 8) & 7) << 4);
}
__device__ __forceinline__ uint32_t pk(float e_lo, float e_hi) {
    uint32_t r;
    asm("cvt.rn.bf16x2.f32 %0, %1, %2;" : "=r"(r) : "f"(e_hi), "f"(e_lo));
    return r;
}
__device__ __forceinline__ void sp(float x, float& hf, float& lf) {
    __nv_bfloat16 hb = __float2bfloat16(x);
    hf = __bfloat162float(hb);
    lf = x - hf;
}
__device__ __forceinline__ void ldsm4(uint32_t addr, uint32_t r[4]) {
    asm volatile("ldmatrix.sync.aligned.m8n8.x4.shared.b16 {%0,%1,%2,%3}, [%4];"
                 : "=r"(r[0]), "=r"(r[1]), "=r"(r[2]), "=r"(r[3]) : "r"(addr));
}
__device__ __forceinline__ void ldsm4t(uint32_t addr, uint32_t r[4]) {
    asm volatile("ldmatrix.sync.aligned.m8n8.x4.trans.shared.b16 {%0,%1,%2,%3}, [%4];"
                 : "=r"(r[0]), "=r"(r[1]), "=r"(r[2]), "=r"(r[3]) : "r"(addr));
}
__device__ __forceinline__ void mma16816(float c[4], const uint32_t a[4],
                                         uint32_t b0, uint32_t b1) {
    asm volatile(
        "mma.sync.aligned.m16n8k16.row.col.f32.bf16.bf16.f32 "
        "{%0,%1,%2,%3}, {%4,%5,%6,%7}, {%8,%9}, {%0,%1,%2,%3};"
        : "+f"(c[0]), "+f"(c[1]), "+f"(c[2]), "+f"(c[3])
        : "r"(a[0]), "r"(a[1]), "r"(a[2]), "r"(a[3]), "r"(b0), "r"(b1));
}
__device__ __forceinline__ void cpa(uint32_t dst, const void* src) {
    asm volatile("cp.async.cg.shared.global [%0], [%1], 16;" :: "r"(dst), "l"(src));
}
#define CP_COMMIT()  asm volatile("cp.async.commit_group;" ::: "memory")
#define CP_WAIT(n)   asm volatile("cp.async.wait_group %0;" :: "n"(n) : "memory")

// ===========================================================================
// Kernel 2: tensor-core attention via mma.sync, double-buffered cp.async KV.
// smem: Q hi/lo (64KB) + 2 KV buffers (64KB each) = 192KB.
// ===========================================================================
#define QHI 0
#define QLO 32768
#define BUF0 65536
#define BUFSTRIDE 65536
#define BKHI 0
#define BKLO 16384
#define BVHI 32768
#define BVLO 49152
#define ATTN_SMEM 196608

// Prefetch K/V hi/lo tile kt (64 rows x 128 cols) into buffer `buf`.
__device__ __forceinline__ void prefetch_kv(uint32_t sb, int buf,
                                            const __nv_bfloat16* Kh, const __nv_bfloat16* Kl,
                                            const __nv_bfloat16* Vh, const __nv_bfloat16* Vl,
                                            int kt, int tid) {
    uint32_t base = sb + BUF0 + buf * BUFSTRIDE;
    size_t goff = (size_t)kt * 64 * 128;
#pragma unroll
    for (int it = 0; it < 4; it++) {
        int idx = tid + it * 256;
        int r = idx >> 4, s = idx & 15;
        uint32_t o = swz((uint32_t)(r * 256 + s * 16));
        size_t ge = goff + (size_t)r * 128 + s * 8;
        cpa(base + BKHI + o, Kh + ge);
        cpa(base + BKLO + o, Kl + ge);
        cpa(base + BVHI + o, Vh + ge);
        cpa(base + BVLO + o, Vl + ge);
    }
}

__global__ __launch_bounds__(256, 1)
void attn_mma(float* __restrict__ out)
{
    extern __shared__ char sm[];
    const uint32_t sb = (uint32_t)__cvta_generic_to_shared(sm);
    const int tid  = threadIdx.x;
    const int wid  = tid >> 5;
    const int lane = tid & 31;
    const int bh = blockIdx.y;
    const int q0 = blockIdx.x * 128;
    const int m0w = wid * 16;

    const __nv_bfloat16* Qh = g_Qhi + ((size_t)bh * Ss + q0) * Dd;
    const __nv_bfloat16* Ql = g_Qlo + ((size_t)bh * Ss + q0) * Dd;
    const __nv_bfloat16* Kh = g_Khi + (size_t)bh * Ss * Dd;
    const __nv_bfloat16* Kl = g_Klo + (size_t)bh * Ss * Dd;
    const __nv_bfloat16* Vh = g_Vhi + (size_t)bh * Ss * Dd;
    const __nv_bfloat16* Vl = g_Vlo + (size_t)bh * Ss * Dd;

    // Stage Q hi/lo (128 rows x 16 chunks, both arrays) via cp.async
#pragma unroll
    for (int it = 0; it < 8; it++) {
        int idx = tid + it * 256;
        int r = idx >> 4, s = idx & 15;
        uint32_t o = swz((uint32_t)(r * 256 + s * 16));
        size_t ge = (size_t)r * 128 + s * 8;
        cpa(sb + QHI + o, Qh + ge);
        cpa(sb + QLO + o, Ql + ge);
    }
    // Prefetch KV tile 0 into buffer 0, commit together with Q
    prefetch_kv(sb, 0, Kh, Kl, Vh, Vl, 0, tid);
    CP_COMMIT();

    // ldmatrix lane-address components
    const int l15 = lane & 15;
    const int lhi8 = (lane >> 4) << 3;
    const int bl_row = ((lane >> 4) << 3) + (lane & 7);
    const int bl_col = ((lane >> 3) & 1) << 3;

    float zacc[16][4];
#pragma unroll
    for (int j = 0; j < 16; j++)
#pragma unroll
        for (int e = 0; e < 4; e++) zacc[j][e] = 0.f;

    for (int kt = 0; kt < 32; kt++) {
        const uint32_t kb = sb + BUF0 + (kt & 1) * BUFSTRIDE;

        if (kt + 1 < 32) {
            prefetch_kv(sb, (kt + 1) & 1, Kh, Kl, Vh, Vl, kt + 1, tid);
            CP_COMMIT();
            CP_WAIT(1);
        } else {
            CP_WAIT(0);
        }
        __syncthreads();   // tile kt visible to all warps

        // ---- GEMM1: S[16,64] = Q . K^T ----
        float sacc[8][4];
#pragma unroll
        for (int j = 0; j < 8; j++)
#pragma unroll
            for (int e = 0; e < 4; e++) sacc[j][e] = 0.f;

#pragma unroll
        for (int kc = 0; kc < 8; kc++) {
            uint32_t ah[4], al[4];
            {
                uint32_t o = swz((uint32_t)((m0w + l15) * 256 + (kc * 16 + lhi8) * 2));
                ldsm4(sb + QHI + o, ah);
                ldsm4(sb + QLO + o, al);
            }
#pragma unroll
            for (int jj = 0; jj < 4; jj++) {
                uint32_t bh4[4], bl4[4];
                uint32_t o = swz((uint32_t)((jj * 16 + bl_row) * 256 + (kc * 16 + bl_col) * 2));
                ldsm4(kb + BKHI + o, bh4);
                ldsm4(kb + BKLO + o, bl4);
                mma16816(sacc[2 * jj],     ah, bh4[0], bh4[1]);
                mma16816(sacc[2 * jj],     ah, bl4[0], bl4[1]);
                mma16816(sacc[2 * jj],     al, bh4[0], bh4[1]);
                mma16816(sacc[2 * jj + 1], ah, bh4[2], bh4[3]);
                mma16816(sacc[2 * jj + 1], ah, bl4[2], bl4[3]);
                mma16816(sacc[2 * jj + 1], al, bh4[2], bh4[3]);
            }
        }

        // ---- GEMM2: Z[16,128] += S . V (S passes through registers) ----
#pragma unroll
        for (int p = 0; p < 4; p++) {
            uint32_t ah[4], al[4];
            {
                float h0, l0, h1, l1;
                sp(sacc[2 * p][0], h0, l0); sp(sacc[2 * p][1], h1, l1);
                ah[0] = pk(h0, h1); al[0] = pk(l0, l1);
                sp(sacc[2 * p][2], h0, l0); sp(sacc[2 * p][3], h1, l1);
                ah[1] = pk(h0, h1); al[1] = pk(l0, l1);
                sp(sacc[2 * p + 1][0], h0, l0); sp(sacc[2 * p + 1][1], h1, l1);
                ah[2] = pk(h0, h1); al[2] = pk(l0, l1);
                sp(sacc[2 * p + 1][2], h0, l0); sp(sacc[2 * p + 1][3], h1, l1);
                ah[3] = pk(h0, h1); al[3] = pk(l0, l1);
            }
#pragma unroll
            for (int np = 0; np < 8; np++) {
                uint32_t bh4[4], bl4[4];
                uint32_t o = swz((uint32_t)((p * 16 + l15) * 256 + (np * 16 + lhi8) * 2));
                ldsm4t(kb + BVHI + o, bh4);
                ldsm4t(kb + BVLO + o, bl4);
                mma16816(zacc[2 * np],     ah, bh4[0], bh4[1]);
                mma16816(zacc[2 * np],     ah, bl4[0], bl4[1]);
                mma16816(zacc[2 * np],     al, bh4[0], bh4[1]);
                mma16816(zacc[2 * np + 1], ah, bh4[2], bh4[3]);
                mma16816(zacc[2 * np + 1], ah, bl4[2], bl4[3]);
                mma16816(zacc[2 * np + 1], al, bh4[2], bh4[3]);
            }
        }
        __syncthreads();   // all warps done with buffer (kt&1) before reuse
    }

    // ---- epilogue: softmax over head dim (128 cols), rows live in quads ----
    const int g = lane >> 2;
    const int t = lane & 3;

#pragma unroll
    for (int half = 0; half < 2; half++) {
        float e[32];
#pragma unroll
        for (int j = 0; j < 16; j++) {
            e[2 * j]     = zacc[j][half * 2];
            e[2 * j + 1] = zacc[j][half * 2 + 1];
        }
        float m = e[0];
#pragma unroll
        for (int c = 1; c < 32; c++) m = fmaxf(m, e[c]);
        m = fmaxf(m, __shfl_xor_sync(0xffffffffu, m, 1));
        m = fmaxf(m, __shfl_xor_sync(0xffffffffu, m, 2));

        float ssum = 0.f;
#pragma unroll
        for (int c = 0; c < 32; c++) { e[c] = expf(e[c] - m); ssum += e[c]; }
        ssum += __shfl_xor_sync(0xffffffffu, ssum, 1);
        ssum += __shfl_xor_sync(0xffffffffu, ssum, 2);
        float inv = 1.0f / ssum;

        int row = q0 + m0w + g + half * 8;
        float* orow = out + ((size_t)bh * Ss + row) * Dd;
#pragma unroll
        for (int j = 0; j < 16; j++) {
            float2 o2 = make_float2(e[2 * j] * inv, e[2 * j + 1] * inv);
            *reinterpret_cast<float2*>(orow + j * 8 + 2 * t) = o2;
        }
    }
}

// ===========================================================================

#define PROJ_SMEM (2 * 128 * TS * (int)sizeof(float))

extern "C" void kernel_launch(void* const* d_in, const int* in_sizes, int n_in,
                              void* d_out, int out_size)
{
    (void)in_sizes; (void)n_in; (void)out_size;
    const float* x  = (const float*)d_in[0];
    const float* Wq = (const float*)d_in[1];
    const float* Wk = (const float*)d_in[2];
    const float* Wv = (const float*)d_in[3];
    float* out = (float*)d_out;

    cudaFuncSetAttribute(proj_kernel, cudaFuncAttributeMaxDynamicSharedMemorySize, PROJ_SMEM);
    cudaFuncSetAttribute(attn_mma, cudaFuncAttributeMaxDynamicSharedMemorySize, ATTN_SMEM);

    proj_kernel<<<dim3(Hh, (Bq * Ss) / 128, 3), 256, PROJ_SMEM>>>(x, Wq, Wk, Wv);
    attn_mma<<<dim3(Ss / 128, Bq * Hh), 256, ATTN_SMEM>>>(out);
}

// round 5
// speedup vs baseline: 3.6896x; 1.2317x over previous
#include <cuda_runtime.h>
#include <cuda_bf16.h>
#include <math.h>
#include <stdint.h>

// Problem constants
#define Bq 4
#define Hh 8
#define Ss 2048
#define Dd 128
#define QKV_ELEMS (Bq*Hh*Ss*Dd)
#define X_ELEMS (Bq*Ss*Dd)       // 1,048,576
#define W_ELEMS (Hh*Dd*Dd)       // 131,072 per matrix
#define SCALE 0.0883883476483184406f   // 1/sqrt(128)

// Pre-split bf16 hi/lo QKV (written by proj_mma, consumed by attn)
__device__ __nv_bfloat16 g_Qhi[QKV_ELEMS];
__device__ __nv_bfloat16 g_Qlo[QKV_ELEMS];
__device__ __nv_bfloat16 g_Khi[QKV_ELEMS];
__device__ __nv_bfloat16 g_Klo[QKV_ELEMS];
__device__ __nv_bfloat16 g_Vhi[QKV_ELEMS];
__device__ __nv_bfloat16 g_Vlo[QKV_ELEMS];

// Split inputs for the projection GEMM
__device__ __nv_bfloat16 g_xhi[X_ELEMS];
__device__ __nv_bfloat16 g_xlo[X_ELEMS];
__device__ __nv_bfloat16 g_Whi[3 * W_ELEMS];
__device__ __nv_bfloat16 g_Wlo[3 * W_ELEMS];

// ===========================================================================
// Common helpers
// ===========================================================================
__device__ __forceinline__ uint32_t swz(uint32_t o) {
    // 256-byte rows of bf16 (128 cols); XOR 16B-chunk index with row%8
    return o ^ (((o >> 8) & 7) << 4);
}
__device__ __forceinline__ uint32_t pk(float e_lo, float e_hi) {
    uint32_t r;
    asm("cvt.rn.bf16x2.f32 %0, %1, %2;" : "=r"(r) : "f"(e_hi), "f"(e_lo));
    return r;
}
__device__ __forceinline__ void sp(float x, float& hf, float& lf) {
    __nv_bfloat16 hb = __float2bfloat16(x);
    hf = __bfloat162float(hb);
    lf = x - hf;
}
__device__ __forceinline__ void ldsm4(uint32_t addr, uint32_t r[4]) {
    asm volatile("ldmatrix.sync.aligned.m8n8.x4.shared.b16 {%0,%1,%2,%3}, [%4];"
                 : "=r"(r[0]), "=r"(r[1]), "=r"(r[2]), "=r"(r[3]) : "r"(addr));
}
__device__ __forceinline__ void ldsm4t(uint32_t addr, uint32_t r[4]) {
    asm volatile("ldmatrix.sync.aligned.m8n8.x4.trans.shared.b16 {%0,%1,%2,%3}, [%4];"
                 : "=r"(r[0]), "=r"(r[1]), "=r"(r[2]), "=r"(r[3]) : "r"(addr));
}
__device__ __forceinline__ void mma16816(float c[4], const uint32_t a[4],
                                         uint32_t b0, uint32_t b1) {
    asm volatile(
        "mma.sync.aligned.m16n8k16.row.col.f32.bf16.bf16.f32 "
        "{%0,%1,%2,%3}, {%4,%5,%6,%7}, {%8,%9}, {%0,%1,%2,%3};"
        : "+f"(c[0]), "+f"(c[1]), "+f"(c[2]), "+f"(c[3])
        : "r"(a[0]), "r"(a[1]), "r"(a[2]), "r"(a[3]), "r"(b0), "r"(b1));
}
__device__ __forceinline__ void cpa(uint32_t dst, const void* src) {
    asm volatile("cp.async.cg.shared.global [%0], [%1], 16;" :: "r"(dst), "l"(src));
}
#define CP_COMMIT()  asm volatile("cp.async.commit_group;" ::: "memory")
#define CP_WAIT(n)   asm volatile("cp.async.wait_group %0;" :: "n"(n) : "memory")

// ===========================================================================
// Kernel 0: fp32 -> bf16 hi/lo split (grid-stride, float4 granularity)
// ===========================================================================
__global__ void split_kernel(const float* __restrict__ src,
                             __nv_bfloat16* __restrict__ hi,
                             __nv_bfloat16* __restrict__ lo, int n4)
{
    for (int i = blockIdx.x * blockDim.x + threadIdx.x; i < n4; i += gridDim.x * blockDim.x) {
        float4 v = *reinterpret_cast<const float4*>(src + 4 * (size_t)i);
        float h0, l0, h1, l1, h2, l2, h3, l3;
        sp(v.x, h0, l0); sp(v.y, h1, l1); sp(v.z, h2, l2); sp(v.w, h3, l3);
        uint2 hp = make_uint2(pk(h0, h1), pk(h2, h3));
        uint2 lp = make_uint2(pk(l0, l1), pk(l2, l3));
        *reinterpret_cast<uint2*>(hi + 4 * (size_t)i) = hp;
        *reinterpret_cast<uint2*>(lo + 4 * (size_t)i) = lp;
    }
}

// ===========================================================================
// Kernel 1: QKV projection on tensor cores.
// grid = (Hh, 64 token-tiles, 3), block = 256. C[128,128] = x_tile . W_h^T.
// smem: x hi/lo 64KB + W hi/lo 64KB = 128KB.
// ===========================================================================
#define PXHI 0
#define PXLO 32768
#define PWHI 65536
#define PWLO 98304
#define PROJ_SMEM 131072

__global__ __launch_bounds__(256, 1)
void proj_mma()
{
    extern __shared__ char sm[];
    const uint32_t sb = (uint32_t)__cvta_generic_to_shared(sm);
    const int tid  = threadIdx.x;
    const int wid  = tid >> 5;
    const int lane = tid & 31;
    const int h     = blockIdx.x;
    const int m0    = blockIdx.y * 128;
    const int which = blockIdx.z;
    const int m0w = wid * 16;

    const __nv_bfloat16* Xh = g_xhi + (size_t)m0 * 128;
    const __nv_bfloat16* Xl = g_xlo + (size_t)m0 * 128;
    const __nv_bfloat16* Wh = g_Whi + (size_t)which * W_ELEMS + (size_t)h * 128 * 128;
    const __nv_bfloat16* Wl = g_Wlo + (size_t)which * W_ELEMS + (size_t)h * 128 * 128;
    __nv_bfloat16* Ohi = (which == 0) ? g_Qhi : (which == 1) ? g_Khi : g_Vhi;
    __nv_bfloat16* Olo = (which == 0) ? g_Qlo : (which == 1) ? g_Klo : g_Vlo;

    // Stage x and W tiles (hi/lo) via cp.async
#pragma unroll
    for (int it = 0; it < 8; it++) {
        int idx = tid + it * 256;
        int r = idx >> 4, s = idx & 15;
        uint32_t o = swz((uint32_t)(r * 256 + s * 16));
        size_t ge = (size_t)r * 128 + s * 8;
        cpa(sb + PXHI + o, Xh + ge);
        cpa(sb + PXLO + o, Xl + ge);
        cpa(sb + PWHI + o, Wh + ge);
        cpa(sb + PWLO + o, Wl + ge);
    }
    CP_COMMIT();
    CP_WAIT(0);
    __syncthreads();

    const int l15 = lane & 15;
    const int lhi8 = (lane >> 4) << 3;
    const int bl_row = ((lane >> 4) << 3) + (lane & 7);
    const int bl_col = ((lane >> 3) & 1) << 3;

    float acc[16][4];
#pragma unroll
    for (int j = 0; j < 16; j++)
#pragma unroll
        for (int e = 0; e < 4; e++) acc[j][e] = 0.f;

#pragma unroll
    for (int kc = 0; kc < 8; kc++) {
        uint32_t ah[4], al[4];
        {
            uint32_t o = swz((uint32_t)((m0w + l15) * 256 + (kc * 16 + lhi8) * 2));
            ldsm4(sb + PXHI + o, ah);
            ldsm4(sb + PXLO + o, al);
        }
#pragma unroll
        for (int jj = 0; jj < 8; jj++) {
            uint32_t bh4[4], bl4[4];
            uint32_t o = swz((uint32_t)((jj * 16 + bl_row) * 256 + (kc * 16 + bl_col) * 2));
            ldsm4(sb + PWHI + o, bh4);
            ldsm4(sb + PWLO + o, bl4);
            mma16816(acc[2 * jj],     ah, bh4[0], bh4[1]);
            mma16816(acc[2 * jj],     ah, bl4[0], bl4[1]);
            mma16816(acc[2 * jj],     al, bh4[0], bh4[1]);
            mma16816(acc[2 * jj + 1], ah, bh4[2], bh4[3]);
            mma16816(acc[2 * jj + 1], ah, bl4[2], bl4[3]);
            mma16816(acc[2 * jj + 1], al, bh4[2], bh4[3]);
        }
    }

    // Epilogue: scale (Q), split to bf16 hi/lo, store packed pairs
    const float mul = (which == 0) ? SCALE : 1.0f;
    const int g = lane >> 2;
    const int t = lane & 3;

#pragma unroll
    for (int half = 0; half < 2; half++) {
        int m = m0 + m0w + g + half * 8;
        int b = m >> 11;
        int s = m & 2047;
        size_t rbase = (((size_t)(b * Hh + h)) * Ss + s) * Dd;
#pragma unroll
        for (int j = 0; j < 16; j++) {
            float v0 = acc[j][half * 2]     * mul;
            float v1 = acc[j][half * 2 + 1] * mul;
            float h0, l0, h1, l1;
            sp(v0, h0, l0);
            sp(v1, h1, l1);
            size_t off = rbase + j * 8 + 2 * t;
            *reinterpret_cast<uint32_t*>(Ohi + off) = pk(h0, h1);
            *reinterpret_cast<uint32_t*>(Olo + off) = pk(l0, l1);
        }
    }
}

// ===========================================================================
// Kernel 2: tensor-core attention via mma.sync, double-buffered cp.async KV.
// smem: Q hi/lo (64KB) + 2 KV buffers (64KB each) = 192KB.
// ===========================================================================
#define QHI 0
#define QLO 32768
#define BUF0 65536
#define BUFSTRIDE 65536
#define BKHI 0
#define BKLO 16384
#define BVHI 32768
#define BVLO 49152
#define ATTN_SMEM 196608

__device__ __forceinline__ void prefetch_kv(uint32_t sb, int buf,
                                            const __nv_bfloat16* Kh, const __nv_bfloat16* Kl,
                                            const __nv_bfloat16* Vh, const __nv_bfloat16* Vl,
                                            int kt, int tid) {
    uint32_t base = sb + BUF0 + buf * BUFSTRIDE;
    size_t goff = (size_t)kt * 64 * 128;
#pragma unroll
    for (int it = 0; it < 4; it++) {
        int idx = tid + it * 256;
        int r = idx >> 4, s = idx & 15;
        uint32_t o = swz((uint32_t)(r * 256 + s * 16));
        size_t ge = goff + (size_t)r * 128 + s * 8;
        cpa(base + BKHI + o, Kh + ge);
        cpa(base + BKLO + o, Kl + ge);
        cpa(base + BVHI + o, Vh + ge);
        cpa(base + BVLO + o, Vl + ge);
    }
}

__global__ __launch_bounds__(256, 1)
void attn_mma(float* __restrict__ out)
{
    extern __shared__ char sm[];
    const uint32_t sb = (uint32_t)__cvta_generic_to_shared(sm);
    const int tid  = threadIdx.x;
    const int wid  = tid >> 5;
    const int lane = tid & 31;
    const int bh = blockIdx.y;
    const int q0 = blockIdx.x * 128;
    const int m0w = wid * 16;

    const __nv_bfloat16* Qh = g_Qhi + ((size_t)bh * Ss + q0) * Dd;
    const __nv_bfloat16* Ql = g_Qlo + ((size_t)bh * Ss + q0) * Dd;
    const __nv_bfloat16* Kh = g_Khi + (size_t)bh * Ss * Dd;
    const __nv_bfloat16* Kl = g_Klo + (size_t)bh * Ss * Dd;
    const __nv_bfloat16* Vh = g_Vhi + (size_t)bh * Ss * Dd;
    const __nv_bfloat16* Vl = g_Vlo + (size_t)bh * Ss * Dd;

#pragma unroll
    for (int it = 0; it < 8; it++) {
        int idx = tid + it * 256;
        int r = idx >> 4, s = idx & 15;
        uint32_t o = swz((uint32_t)(r * 256 + s * 16));
        size_t ge = (size_t)r * 128 + s * 8;
        cpa(sb + QHI + o, Qh + ge);
        cpa(sb + QLO + o, Ql + ge);
    }
    prefetch_kv(sb, 0, Kh, Kl, Vh, Vl, 0, tid);
    CP_COMMIT();

    const int l15 = lane & 15;
    const int lhi8 = (lane >> 4) << 3;
    const int bl_row = ((lane >> 4) << 3) + (lane & 7);
    const int bl_col = ((lane >> 3) & 1) << 3;

    float zacc[16][4];
#pragma unroll
    for (int j = 0; j < 16; j++)
#pragma unroll
        for (int e = 0; e < 4; e++) zacc[j][e] = 0.f;

    for (int kt = 0; kt < 32; kt++) {
        const uint32_t kb = sb + BUF0 + (kt & 1) * BUFSTRIDE;

        if (kt + 1 < 32) {
            prefetch_kv(sb, (kt + 1) & 1, Kh, Kl, Vh, Vl, kt + 1, tid);
            CP_COMMIT();
            CP_WAIT(1);
        } else {
            CP_WAIT(0);
        }
        __syncthreads();

        // ---- GEMM1: S[16,64] = Q . K^T ----
        float sacc[8][4];
#pragma unroll
        for (int j = 0; j < 8; j++)
#pragma unroll
            for (int e = 0; e < 4; e++) sacc[j][e] = 0.f;

#pragma unroll
        for (int kc = 0; kc < 8; kc++) {
            uint32_t ah[4], al[4];
            {
                uint32_t o = swz((uint32_t)((m0w + l15) * 256 + (kc * 16 + lhi8) * 2));
                ldsm4(sb + QHI + o, ah);
                ldsm4(sb + QLO + o, al);
            }
#pragma unroll
            for (int jj = 0; jj < 4; jj++) {
                uint32_t bh4[4], bl4[4];
                uint32_t o = swz((uint32_t)((jj * 16 + bl_row) * 256 + (kc * 16 + bl_col) * 2));
                ldsm4(kb + BKHI + o, bh4);
                ldsm4(kb + BKLO + o, bl4);
                mma16816(sacc[2 * jj],     ah, bh4[0], bh4[1]);
                mma16816(sacc[2 * jj],     ah, bl4[0], bl4[1]);
                mma16816(sacc[2 * jj],     al, bh4[0], bh4[1]);
                mma16816(sacc[2 * jj + 1], ah, bh4[2], bh4[3]);
                mma16816(sacc[2 * jj + 1], ah, bl4[2], bl4[3]);
                mma16816(sacc[2 * jj + 1], al, bh4[2], bh4[3]);
            }
        }

        // ---- GEMM2: Z[16,128] += S . V (S passes through registers) ----
#pragma unroll
        for (int p = 0; p < 4; p++) {
            uint32_t ah[4], al[4];
            {
                float h0, l0, h1, l1;
                sp(sacc[2 * p][0], h0, l0); sp(sacc[2 * p][1], h1, l1);
                ah[0] = pk(h0, h1); al[0] = pk(l0, l1);
                sp(sacc[2 * p][2], h0, l0); sp(sacc[2 * p][3], h1, l1);
                ah[1] = pk(h0, h1); al[1] = pk(l0, l1);
                sp(sacc[2 * p + 1][0], h0, l0); sp(sacc[2 * p + 1][1], h1, l1);
                ah[2] = pk(h0, h1); al[2] = pk(l0, l1);
                sp(sacc[2 * p + 1][2], h0, l0); sp(sacc[2 * p + 1][3], h1, l1);
                ah[3] = pk(h0, h1); al[3] = pk(l0, l1);
            }
#pragma unroll
            for (int np = 0; np < 8; np++) {
                uint32_t bh4[4], bl4[4];
                uint32_t o = swz((uint32_t)((p * 16 + l15) * 256 + (np * 16 + lhi8) * 2));
                ldsm4t(kb + BVHI + o, bh4);
                ldsm4t(kb + BVLO + o, bl4);
                mma16816(zacc[2 * np],     ah, bh4[0], bh4[1]);
                mma16816(zacc[2 * np],     ah, bl4[0], bl4[1]);
                mma16816(zacc[2 * np],     al, bh4[0], bh4[1]);
                mma16816(zacc[2 * np + 1], ah, bh4[2], bh4[3]);
                mma16816(zacc[2 * np + 1], ah, bl4[2], bl4[3]);
                mma16816(zacc[2 * np + 1], al, bh4[2], bh4[3]);
            }
        }
        __syncthreads();
    }

    // ---- epilogue: softmax over head dim ----
    const int g = lane >> 2;
    const int t = lane & 3;

#pragma unroll
    for (int half = 0; half < 2; half++) {
        float e[32];
#pragma unroll
        for (int j = 0; j < 16; j++) {
            e[2 * j]     = zacc[j][half * 2];
            e[2 * j + 1] = zacc[j][half * 2 + 1];
        }
        float m = e[0];
#pragma unroll
        for (int c = 1; c < 32; c++) m = fmaxf(m, e[c]);
        m = fmaxf(m, __shfl_xor_sync(0xffffffffu, m, 1));
        m = fmaxf(m, __shfl_xor_sync(0xffffffffu, m, 2));

        float ssum = 0.f;
#pragma unroll
        for (int c = 0; c < 32; c++) { e[c] = __expf(e[c] - m); ssum += e[c]; }
        ssum += __shfl_xor_sync(0xffffffffu, ssum, 1);
        ssum += __shfl_xor_sync(0xffffffffu, ssum, 2);
        float inv = 1.0f / ssum;

        int row = q0 + m0w + g + half * 8;
        float* orow = out + ((size_t)bh * Ss + row) * Dd;
#pragma unroll
        for (int j = 0; j < 16; j++) {
            float2 o2 = make_float2(e[2 * j] * inv, e[2 * j + 1] * inv);
            *reinterpret_cast<float2*>(orow + j * 8 + 2 * t) = o2;
        }
    }
}

// ===========================================================================

extern "C" void kernel_launch(void* const* d_in, const int* in_sizes, int n_in,
                              void* d_out, int out_size)
{
    (void)in_sizes; (void)n_in; (void)out_size;
    const float* x  = (const float*)d_in[0];
    const float* Wq = (const float*)d_in[1];
    const float* Wk = (const float*)d_in[2];
    const float* Wv = (const float*)d_in[3];
    float* out = (float*)d_out;

    cudaFuncSetAttribute(proj_mma, cudaFuncAttributeMaxDynamicSharedMemorySize, PROJ_SMEM);
    cudaFuncSetAttribute(attn_mma, cudaFuncAttributeMaxDynamicSharedMemorySize, ATTN_SMEM);

    __nv_bfloat16 *xhi_p, *xlo_p, *whi_p, *wlo_p;
    cudaGetSymbolAddress((void**)&xhi_p, g_xhi);
    cudaGetSymbolAddress((void**)&xlo_p, g_xlo);
    cudaGetSymbolAddress((void**)&whi_p, g_Whi);
    cudaGetSymbolAddress((void**)&wlo_p, g_Wlo);

    split_kernel<<<512, 256>>>(x,  xhi_p, xlo_p, X_ELEMS / 4);
    split_kernel<<<192, 256>>>(Wq, whi_p,               wlo_p,               W_ELEMS / 4);
    split_kernel<<<192, 256>>>(Wk, whi_p + W_ELEMS,     wlo_p + W_ELEMS,     W_ELEMS / 4);
    split_kernel<<<192, 256>>>(Wv, whi_p + 2 * W_ELEMS, wlo_p + 2 * W_ELEMS, W_ELEMS / 4);

    proj_mma<<<dim3(Hh, (Bq * Ss) / 128, 3), 256, PROJ_SMEM>>>();
    attn_mma<<<dim3(Ss / 128, Bq * Hh), 256, ATTN_SMEM>>>(out);
}

// round 7
// speedup vs baseline: 4.2102x; 1.1411x over previous
#include <cuda_runtime.h>
#include <cuda_bf16.h>
#include <math.h>
#include <stdint.h>

// Problem constants
#define Bq 4
#define Hh 8
#define Ss 2048
#define Dd 128
#define QKV_ELEMS (Bq*Hh*Ss*Dd)
#define X_ELEMS (Bq*Ss*Dd)       // 1,048,576
#define W_ELEMS (Hh*Dd*Dd)       // 131,072 per matrix
#define SCALE 0.0883883476483184406f   // 1/sqrt(128)

__device__ __nv_bfloat16 g_Qhi[QKV_ELEMS];
__device__ __nv_bfloat16 g_Qlo[QKV_ELEMS];
__device__ __nv_bfloat16 g_Khi[QKV_ELEMS];
__device__ __nv_bfloat16 g_Klo[QKV_ELEMS];
__device__ __nv_bfloat16 g_Vhi[QKV_ELEMS];
__device__ __nv_bfloat16 g_Vlo[QKV_ELEMS];

__device__ __nv_bfloat16 g_xhi[X_ELEMS];
__device__ __nv_bfloat16 g_xlo[X_ELEMS];
__device__ __nv_bfloat16 g_Whi[3 * W_ELEMS];
__device__ __nv_bfloat16 g_Wlo[3 * W_ELEMS];

#define ATTN_GRID 296
#define UNITS 1024
__device__ int g_ctr;

// ===========================================================================
// Common helpers
// ===========================================================================
__device__ __forceinline__ uint32_t swz(uint32_t o) {
    return o ^ (((o >> 8) & 7) << 4);
}
__device__ __forceinline__ uint32_t pk(float e_lo, float e_hi) {
    uint32_t r;
    asm("cvt.rn.bf16x2.f32 %0, %1, %2;" : "=r"(r) : "f"(e_hi), "f"(e_lo));
    return r;
}
__device__ __forceinline__ void sp(float x, float& hf, float& lf) {
    __nv_bfloat16 hb = __float2bfloat16(x);
    hf = __bfloat162float(hb);
    lf = x - hf;
}
__device__ __forceinline__ void ldsm4(uint32_t addr, uint32_t r[4]) {
    asm volatile("ldmatrix.sync.aligned.m8n8.x4.shared.b16 {%0,%1,%2,%3}, [%4];"
                 : "=r"(r[0]), "=r"(r[1]), "=r"(r[2]), "=r"(r[3]) : "r"(addr));
}
__device__ __forceinline__ void ldsm4t(uint32_t addr, uint32_t r[4]) {
    asm volatile("ldmatrix.sync.aligned.m8n8.x4.trans.shared.b16 {%0,%1,%2,%3}, [%4];"
                 : "=r"(r[0]), "=r"(r[1]), "=r"(r[2]), "=r"(r[3]) : "r"(addr));
}
__device__ __forceinline__ void mma16816(float c[4], const uint32_t a[4],
                                         uint32_t b0, uint32_t b1) {
    asm volatile(
        "mma.sync.aligned.m16n8k16.row.col.f32.bf16.bf16.f32 "
        "{%0,%1,%2,%3}, {%4,%5,%6,%7}, {%8,%9}, {%0,%1,%2,%3};"
        : "+f"(c[0]), "+f"(c[1]), "+f"(c[2]), "+f"(c[3])
        : "r"(a[0]), "r"(a[1]), "r"(a[2]), "r"(a[3]), "r"(b0), "r"(b1));
}
__device__ __forceinline__ void cpa(uint32_t dst, const void* src) {
    asm volatile("cp.async.cg.shared.global [%0], [%1], 16;" :: "r"(dst), "l"(src));
}
#define CP_COMMIT()  asm volatile("cp.async.commit_group;" ::: "memory")
#define CP_WAIT(n)   asm volatile("cp.async.wait_group %0;" :: "n"(n) : "memory")

// ===========================================================================
// Kernel 0a: init work counter
// ===========================================================================
__global__ void init_ctr() { g_ctr = ATTN_GRID; }

// ===========================================================================
// Kernel 0b: fused fp32 -> bf16 hi/lo split for x, Wq, Wk, Wv.
// ===========================================================================
#define X4 (X_ELEMS / 4)        // 262144
#define W4 (W_ELEMS / 4)        // 32768
#define TOT4 (X4 + 3 * W4)      // 360448

__global__ __launch_bounds__(256)
void split_all(const float* __restrict__ x, const float* __restrict__ wq,
               const float* __restrict__ wk, const float* __restrict__ wv)
{
    int i = blockIdx.x * 256 + threadIdx.x;
    if (i >= TOT4) return;
    const float* src;
    __nv_bfloat16 *hi, *lo;
    size_t off;
    if (i < X4) {
        src = x; hi = g_xhi; lo = g_xlo; off = (size_t)i * 4;
    } else {
        int j = i - X4;
        int w = j / W4;
        int r = j - w * W4;
        src = (w == 0) ? wq : (w == 1) ? wk : wv;
        hi = g_Whi + (size_t)w * W_ELEMS;
        lo = g_Wlo + (size_t)w * W_ELEMS;
        off = (size_t)r * 4;
    }
    float4 v = *reinterpret_cast<const float4*>(src + off);
    float h0, l0, h1, l1, h2, l2, h3, l3;
    sp(v.x, h0, l0); sp(v.y, h1, l1); sp(v.z, h2, l2); sp(v.w, h3, l3);
    *reinterpret_cast<uint2*>(hi + off) = make_uint2(pk(h0, h1), pk(h2, h3));
    *reinterpret_cast<uint2*>(lo + off) = make_uint2(pk(l0, l1), pk(l2, l3));
}

// ===========================================================================
// Kernel 1: QKV projection on tensor cores, 4 m-tiles per CTA.
// grid = (Hh, 16, 3), block = 256.
// smem: W hi/lo 64KB + 2 x-buffers (64KB each) = 192KB.
// ===========================================================================
#define PWHI 0
#define PWLO 32768
#define PXBUF 65536
#define PXSTRIDE 65536
#define PXHI 0
#define PXLO 32768
#define PROJ_SMEM 196608

__global__ __launch_bounds__(256, 1)
void proj_mma()
{
    extern __shared__ char sm[];
    const uint32_t sb = (uint32_t)__cvta_generic_to_shared(sm);
    const int tid  = threadIdx.x;
    const int wid  = tid >> 5;
    const int lane = tid & 31;
    const int h     = blockIdx.x;
    const int which = blockIdx.z;
    const int m0w = wid * 16;

    const __nv_bfloat16* Wh = g_Whi + (size_t)which * W_ELEMS + (size_t)h * 128 * 128;
    const __nv_bfloat16* Wl = g_Wlo + (size_t)which * W_ELEMS + (size_t)h * 128 * 128;
    __nv_bfloat16* Ohi = (which == 0) ? g_Qhi : (which == 1) ? g_Khi : g_Vhi;
    __nv_bfloat16* Olo = (which == 0) ? g_Qlo : (which == 1) ? g_Klo : g_Vlo;

#pragma unroll
    for (int it = 0; it < 8; it++) {
        int idx = tid + it * 256;
        int r = idx >> 4, s = idx & 15;
        uint32_t o = swz((uint32_t)(r * 256 + s * 16));
        size_t ge = (size_t)r * 128 + s * 8;
        cpa(sb + PWHI + o, Wh + ge);
        cpa(sb + PWLO + o, Wl + ge);
    }
    {
        size_t xoff = (size_t)(blockIdx.y * 4) * 128 * 128;
#pragma unroll
        for (int it = 0; it < 8; it++) {
            int idx = tid + it * 256;
            int r = idx >> 4, s = idx & 15;
            uint32_t o = swz((uint32_t)(r * 256 + s * 16));
            size_t ge = xoff + (size_t)r * 128 + s * 8;
            cpa(sb + PXBUF + PXHI + o, g_xhi + ge);
            cpa(sb + PXBUF + PXLO + o, g_xlo + ge);
        }
    }
    CP_COMMIT();

    const int l15 = lane & 15;
    const int lhi8 = (lane >> 4) << 3;
    const int bl_row = ((lane >> 4) << 3) + (lane & 7);
    const int bl_col = ((lane >> 3) & 1) << 3;
    const float mul = (which == 0) ? SCALE : 1.0f;
    const int g = lane >> 2;
    const int t = lane & 3;

    for (int mt = 0; mt < 4; mt++) {
        const uint32_t xb = sb + PXBUF + (mt & 1) * PXSTRIDE;
        const int m0 = (blockIdx.y * 4 + mt) * 128;

        if (mt + 1 < 4) {
            size_t xoff = (size_t)(m0 + 128) * 128;
#pragma unroll
            for (int it = 0; it < 8; it++) {
                int idx = tid + it * 256;
                int r = idx >> 4, s = idx & 15;
                uint32_t o = swz((uint32_t)(r * 256 + s * 16));
                size_t ge = xoff + (size_t)r * 128 + s * 8;
                uint32_t dst = sb + PXBUF + ((mt + 1) & 1) * PXSTRIDE;
                cpa(dst + PXHI + o, g_xhi + ge);
                cpa(dst + PXLO + o, g_xlo + ge);
            }
            CP_COMMIT();
            CP_WAIT(1);
        } else {
            CP_WAIT(0);
        }
        __syncthreads();

        float acc[16][4];
#pragma unroll
        for (int j = 0; j < 16; j++)
#pragma unroll
            for (int e = 0; e < 4; e++) acc[j][e] = 0.f;

#pragma unroll
        for (int kc = 0; kc < 8; kc++) {
            uint32_t ah[4], al[4];
            {
                uint32_t o = swz((uint32_t)((m0w + l15) * 256 + (kc * 16 + lhi8) * 2));
                ldsm4(xb + PXHI + o, ah);
                ldsm4(xb + PXLO + o, al);
            }
#pragma unroll
            for (int jj = 0; jj < 8; jj++) {
                uint32_t bh4[4], bl4[4];
                uint32_t o = swz((uint32_t)((jj * 16 + bl_row) * 256 + (kc * 16 + bl_col) * 2));
                ldsm4(sb + PWHI + o, bh4);
                ldsm4(sb + PWLO + o, bl4);
                mma16816(acc[2 * jj],     ah, bh4[0], bh4[1]);
                mma16816(acc[2 * jj],     ah, bl4[0], bl4[1]);
                mma16816(acc[2 * jj],     al, bh4[0], bh4[1]);
                mma16816(acc[2 * jj + 1], ah, bh4[2], bh4[3]);
                mma16816(acc[2 * jj + 1], ah, bl4[2], bl4[3]);
                mma16816(acc[2 * jj + 1], al, bh4[2], bh4[3]);
            }
        }

#pragma unroll
        for (int half = 0; half < 2; half++) {
            int m = m0 + m0w + g + half * 8;
            int b = m >> 11;
            int s = m & 2047;
            size_t rbase = (((size_t)(b * Hh + h)) * Ss + s) * Dd;
#pragma unroll
            for (int j = 0; j < 16; j++) {
                float v0 = acc[j][half * 2]     * mul;
                float v1 = acc[j][half * 2 + 1] * mul;
                float h0, l0, h1, l1;
                sp(v0, h0, l0);
                sp(v1, h1, l1);
                size_t off = rbase + j * 8 + 2 * t;
                *reinterpret_cast<uint32_t*>(Ohi + off) = pk(h0, h1);
                *reinterpret_cast<uint32_t*>(Olo + off) = pk(l0, l1);
            }
        }
        __syncthreads();
    }
}

// ===========================================================================
// Kernel 2: persistent tensor-core attention, 128 threads, 2 CTAs/SM.
// Unit = (bh, 64-row q-tile); KV tiles of 32 rows, double-buffered.
// smem: Q hi/lo 32KB + 2 KV buffers (32KB each) + bcast slot = ~96KB.
// ===========================================================================
#define QHI 0
#define QLO 16384
#define BUF0 32768
#define BUFSTRIDE 32768
#define BKHI 0
#define BKLO 8192
#define BVHI 16384
#define BVLO 24576
#define UNIT_SLOT 98304
#define ATTN_SMEM 98432

__device__ __forceinline__ void prefetch_kv32(uint32_t sb, int buf,
                                              const __nv_bfloat16* Kh, const __nv_bfloat16* Kl,
                                              const __nv_bfloat16* Vh, const __nv_bfloat16* Vl,
                                              int kt, int tid) {
    uint32_t base = sb + BUF0 + buf * BUFSTRIDE;
    size_t goff = (size_t)kt * 32 * 128;
#pragma unroll
    for (int it = 0; it < 4; it++) {
        int idx = tid + it * 128;
        int r = idx >> 4, s = idx & 15;
        uint32_t o = swz((uint32_t)(r * 256 + s * 16));
        size_t ge = goff + (size_t)r * 128 + s * 8;
        cpa(base + BKHI + o, Kh + ge);
        cpa(base + BKLO + o, Kl + ge);
        cpa(base + BVHI + o, Vh + ge);
        cpa(base + BVLO + o, Vl + ge);
    }
}

__global__ __launch_bounds__(128, 2)
void attn_mma(float* __restrict__ out)
{
    extern __shared__ char sm[];
    const uint32_t sb = (uint32_t)__cvta_generic_to_shared(sm);
    volatile int* unit_sh = reinterpret_cast<volatile int*>(sm + UNIT_SLOT);
    const int tid  = threadIdx.x;
    const int wid  = tid >> 5;
    const int lane = tid & 31;
    const int m0w = wid * 16;

    const int l15 = lane & 15;
    const int lhi8 = (lane >> 4) << 3;
    const int bl_row = ((lane >> 4) << 3) + (lane & 7);
    const int bl_col = ((lane >> 3) & 1) << 3;
    const int g = lane >> 2;
    const int t = lane & 3;

    int unit = blockIdx.x;
    while (unit < UNITS) {
        const int bh = unit >> 5;
        const int q0 = (unit & 31) << 6;

        const __nv_bfloat16* Qh = g_Qhi + ((size_t)bh * Ss + q0) * Dd;
        const __nv_bfloat16* Ql = g_Qlo + ((size_t)bh * Ss + q0) * Dd;
        const __nv_bfloat16* Kh = g_Khi + (size_t)bh * Ss * Dd;
        const __nv_bfloat16* Kl = g_Klo + (size_t)bh * Ss * Dd;
        const __nv_bfloat16* Vh = g_Vhi + (size_t)bh * Ss * Dd;
        const __nv_bfloat16* Vl = g_Vlo + (size_t)bh * Ss * Dd;

        // Stage Q (64 x 128 hi/lo) + prefetch KV tile 0
#pragma unroll
        for (int it = 0; it < 8; it++) {
            int idx = tid + it * 128;
            int r = idx >> 4, s = idx & 15;
            uint32_t o = swz((uint32_t)(r * 256 + s * 16));
            size_t ge = (size_t)r * 128 + s * 8;
            cpa(sb + QHI + o, Qh + ge);
            cpa(sb + QLO + o, Ql + ge);
        }
        prefetch_kv32(sb, 0, Kh, Kl, Vh, Vl, 0, tid);
        CP_COMMIT();

        float zacc[16][4];
#pragma unroll
        for (int j = 0; j < 16; j++)
#pragma unroll
            for (int e = 0; e < 4; e++) zacc[j][e] = 0.f;

        for (int kt = 0; kt < 64; kt++) {
            const uint32_t kb = sb + BUF0 + (kt & 1) * BUFSTRIDE;

            if (kt + 1 < 64) {
                prefetch_kv32(sb, (kt + 1) & 1, Kh, Kl, Vh, Vl, kt + 1, tid);
                CP_COMMIT();
                CP_WAIT(1);
            } else {
                CP_WAIT(0);
            }
            __syncthreads();

            // ---- GEMM1: S[16,32] = Q . K^T ----
            float sacc[4][4];
#pragma unroll
            for (int j = 0; j < 4; j++)
#pragma unroll
                for (int e = 0; e < 4; e++) sacc[j][e] = 0.f;

#pragma unroll
            for (int kc = 0; kc < 8; kc++) {
                uint32_t ah[4], al[4];
                {
                    uint32_t o = swz((uint32_t)((m0w + l15) * 256 + (kc * 16 + lhi8) * 2));
                    ldsm4(sb + QHI + o, ah);
                    ldsm4(sb + QLO + o, al);
                }
#pragma unroll
                for (int jj = 0; jj < 2; jj++) {
                    uint32_t bh4[4], bl4[4];
                    uint32_t o = swz((uint32_t)((jj * 16 + bl_row) * 256 + (kc * 16 + bl_col) * 2));
                    ldsm4(kb + BKHI + o, bh4);
                    ldsm4(kb + BKLO + o, bl4);
                    mma16816(sacc[2 * jj],     ah, bh4[0], bh4[1]);
                    mma16816(sacc[2 * jj],     ah, bl4[0], bl4[1]);
                    mma16816(sacc[2 * jj],     al, bh4[0], bh4[1]);
                    mma16816(sacc[2 * jj + 1], ah, bh4[2], bh4[3]);
                    mma16816(sacc[2 * jj + 1], ah, bl4[2], bl4[3]);
                    mma16816(sacc[2 * jj + 1], al, bh4[2], bh4[3]);
                }
            }

            // ---- GEMM2: Z[16,128] += S . V ----
#pragma unroll
            for (int p = 0; p < 2; p++) {
                uint32_t ah[4], al[4];
                {
                    float h0, l0, h1, l1;
                    sp(sacc[2 * p][0], h0, l0); sp(sacc[2 * p][1], h1, l1);
                    ah[0] = pk(h0, h1); al[0] = pk(l0, l1);
                    sp(sacc[2 * p][2], h0, l0); sp(sacc[2 * p][3], h1, l1);
                    ah[1] = pk(h0, h1); al[1] = pk(l0, l1);
                    sp(sacc[2 * p + 1][0], h0, l0); sp(sacc[2 * p + 1][1], h1, l1);
                    ah[2] = pk(h0, h1); al[2] = pk(l0, l1);
                    sp(sacc[2 * p + 1][2], h0, l0); sp(sacc[2 * p + 1][3], h1, l1);
                    ah[3] = pk(h0, h1); al[3] = pk(l0, l1);
                }
#pragma unroll
                for (int np = 0; np < 8; np++) {
                    uint32_t bh4[4], bl4[4];
                    uint32_t o = swz((uint32_t)((p * 16 + l15) * 256 + (np * 16 + lhi8) * 2));
                    ldsm4t(kb + BVHI + o, bh4);
                    ldsm4t(kb + BVLO + o, bl4);
                    mma16816(zacc[2 * np],     ah, bh4[0], bh4[1]);
                    mma16816(zacc[2 * np],     ah, bl4[0], bl4[1]);
                    mma16816(zacc[2 * np],     al, bh4[0], bh4[1]);
                    mma16816(zacc[2 * np + 1], ah, bh4[2], bh4[3]);
                    mma16816(zacc[2 * np + 1], ah, bl4[2], bl4[3]);
                    mma16816(zacc[2 * np + 1], al, bh4[2], bh4[3]);
                }
            }
            __syncthreads();
        }

        // ---- epilogue: softmax over head dim ----
#pragma unroll
        for (int half = 0; half < 2; half++) {
            float e[32];
#pragma unroll
            for (int j = 0; j < 16; j++) {
                e[2 * j]     = zacc[j][half * 2];
                e[2 * j + 1] = zacc[j][half * 2 + 1];
            }
            float m = e[0];
#pragma unroll
            for (int c = 1; c < 32; c++) m = fmaxf(m, e[c]);
            m = fmaxf(m, __shfl_xor_sync(0xffffffffu, m, 1));
            m = fmaxf(m, __shfl_xor_sync(0xffffffffu, m, 2));

            float ssum = 0.f;
#pragma unroll
            for (int c = 0; c < 32; c++) { e[c] = __expf(e[c] - m); ssum += e[c]; }
            ssum += __shfl_xor_sync(0xffffffffu, ssum, 1);
            ssum += __shfl_xor_sync(0xffffffffu, ssum, 2);
            float inv = 1.0f / ssum;

            int row = q0 + m0w + g + half * 8;
            float* orow = out + ((size_t)bh * Ss + row) * Dd;
#pragma unroll
            for (int j = 0; j < 16; j++) {
                float2 o2 = make_float2(e[2 * j] * inv, e[2 * j + 1] * inv);
                *reinterpret_cast<float2*>(orow + j * 8 + 2 * t) = o2;
            }
        }

        // ---- work stealing: ONE fetch per CTA, broadcast via smem ----
        if (tid == 0) *unit_sh = atomicAdd(&g_ctr, 1);
        __syncthreads();
        unit = *unit_sh;
        __syncthreads();
    }
}

// ===========================================================================

extern "C" void kernel_launch(void* const* d_in, const int* in_sizes, int n_in,
                              void* d_out, int out_size)
{
    (void)in_sizes; (void)n_in; (void)out_size;
    const float* x  = (const float*)d_in[0];
    const float* Wq = (const float*)d_in[1];
    const float* Wk = (const float*)d_in[2];
    const float* Wv = (const float*)d_in[3];
    float* out = (float*)d_out;

    cudaFuncSetAttribute(proj_mma, cudaFuncAttributeMaxDynamicSharedMemorySize, PROJ_SMEM);
    cudaFuncSetAttribute(attn_mma, cudaFuncAttributeMaxDynamicSharedMemorySize, ATTN_SMEM);

    init_ctr<<<1, 1>>>();
    split_all<<<(TOT4 + 255) / 256, 256>>>(x, Wq, Wk, Wv);
    proj_mma<<<dim3(Hh, 16, 3), 256, PROJ_SMEM>>>();
    attn_mma<<<ATTN_GRID, 128, ATTN_SMEM>>>(out);
}

// round 8
// speedup vs baseline: 4.2262x; 1.0038x over previous
#include <cuda_runtime.h>
#include <cuda_bf16.h>
#include <math.h>
#include <stdint.h>

// Problem constants
#define Bq 4
#define Hh 8
#define Ss 2048
#define Dd 128
#define QKV_ELEMS (Bq*Hh*Ss*Dd)
#define X_ELEMS (Bq*Ss*Dd)       // 1,048,576
#define W_ELEMS (Hh*Dd*Dd)       // 131,072 per matrix
#define SCALE 0.0883883476483184406f   // 1/sqrt(128)

__device__ __nv_bfloat16 g_Qhi[QKV_ELEMS];
__device__ __nv_bfloat16 g_Qlo[QKV_ELEMS];
__device__ __nv_bfloat16 g_Khi[QKV_ELEMS];
__device__ __nv_bfloat16 g_Klo[QKV_ELEMS];
__device__ __nv_bfloat16 g_Vhi[QKV_ELEMS];
__device__ __nv_bfloat16 g_Vlo[QKV_ELEMS];

__device__ __nv_bfloat16 g_xhi[X_ELEMS];
__device__ __nv_bfloat16 g_xlo[X_ELEMS];
__device__ __nv_bfloat16 g_Whi[3 * W_ELEMS];
__device__ __nv_bfloat16 g_Wlo[3 * W_ELEMS];

#define ATTN_GRID 296
#define UNITS 1024
__device__ int g_ctr;

// ===========================================================================
// Common helpers
// ===========================================================================
__device__ __forceinline__ uint32_t swz(uint32_t o) {
    return o ^ (((o >> 8) & 7) << 4);
}
__device__ __forceinline__ uint32_t pk(float e_lo, float e_hi) {
    uint32_t r;
    asm("cvt.rn.bf16x2.f32 %0, %1, %2;" : "=r"(r) : "f"(e_hi), "f"(e_lo));
    return r;
}
__device__ __forceinline__ void sp(float x, float& hf, float& lf) {
    __nv_bfloat16 hb = __float2bfloat16(x);
    hf = __bfloat162float(hb);
    lf = x - hf;
}
__device__ __forceinline__ void ldsm4(uint32_t addr, uint32_t r[4]) {
    asm volatile("ldmatrix.sync.aligned.m8n8.x4.shared.b16 {%0,%1,%2,%3}, [%4];"
                 : "=r"(r[0]), "=r"(r[1]), "=r"(r[2]), "=r"(r[3]) : "r"(addr));
}
__device__ __forceinline__ void ldsm4t(uint32_t addr, uint32_t r[4]) {
    asm volatile("ldmatrix.sync.aligned.m8n8.x4.trans.shared.b16 {%0,%1,%2,%3}, [%4];"
                 : "=r"(r[0]), "=r"(r[1]), "=r"(r[2]), "=r"(r[3]) : "r"(addr));
}
__device__ __forceinline__ void mma16816(float c[4], const uint32_t a[4],
                                         uint32_t b0, uint32_t b1) {
    asm volatile(
        "mma.sync.aligned.m16n8k16.row.col.f32.bf16.bf16.f32 "
        "{%0,%1,%2,%3}, {%4,%5,%6,%7}, {%8,%9}, {%0,%1,%2,%3};"
        : "+f"(c[0]), "+f"(c[1]), "+f"(c[2]), "+f"(c[3])
        : "r"(a[0]), "r"(a[1]), "r"(a[2]), "r"(a[3]), "r"(b0), "r"(b1));
}
__device__ __forceinline__ void cpa(uint32_t dst, const void* src) {
    asm volatile("cp.async.cg.shared.global [%0], [%1], 16;" :: "r"(dst), "l"(src));
}
#define CP_COMMIT()  asm volatile("cp.async.commit_group;" ::: "memory")
#define CP_WAIT(n)   asm volatile("cp.async.wait_group %0;" :: "n"(n) : "memory")

// ===========================================================================
// Kernel 0: fused fp32 -> bf16 hi/lo split for x, Wq, Wk, Wv (+ ctr init)
// ===========================================================================
#define X4 (X_ELEMS / 4)        // 262144
#define W4 (W_ELEMS / 4)        // 32768
#define TOT4 (X4 + 3 * W4)      // 360448

__global__ __launch_bounds__(256)
void split_all(const float* __restrict__ x, const float* __restrict__ wq,
               const float* __restrict__ wk, const float* __restrict__ wv)
{
    if (blockIdx.x == 0 && threadIdx.x == 0) g_ctr = ATTN_GRID;

    int i = blockIdx.x * 256 + threadIdx.x;
    if (i >= TOT4) return;
    const float* src;
    __nv_bfloat16 *hi, *lo;
    size_t off;
    if (i < X4) {
        src = x; hi = g_xhi; lo = g_xlo; off = (size_t)i * 4;
    } else {
        int j = i - X4;
        int w = j / W4;
        int r = j - w * W4;
        src = (w == 0) ? wq : (w == 1) ? wk : wv;
        hi = g_Whi + (size_t)w * W_ELEMS;
        lo = g_Wlo + (size_t)w * W_ELEMS;
        off = (size_t)r * 4;
    }
    float4 v = *reinterpret_cast<const float4*>(src + off);
    float h0, l0, h1, l1, h2, l2, h3, l3;
    sp(v.x, h0, l0); sp(v.y, h1, l1); sp(v.z, h2, l2); sp(v.w, h3, l3);
    *reinterpret_cast<uint2*>(hi + off) = make_uint2(pk(h0, h1), pk(h2, h3));
    *reinterpret_cast<uint2*>(lo + off) = make_uint2(pk(l0, l1), pk(l2, l3));
}

// ===========================================================================
// Kernel 1: QKV projection on tensor cores, 4 m-tiles per CTA.
// grid = (Hh, 16, 3), block = 256.
// smem: W hi/lo 64KB + 2 x-buffers (64KB each) = 192KB.
// ===========================================================================
#define PWHI 0
#define PWLO 32768
#define PXBUF 65536
#define PXSTRIDE 65536
#define PXHI 0
#define PXLO 32768
#define PROJ_SMEM 196608

__global__ __launch_bounds__(256, 1)
void proj_mma()
{
    extern __shared__ char sm[];
    const uint32_t sb = (uint32_t)__cvta_generic_to_shared(sm);
    const int tid  = threadIdx.x;
    const int wid  = tid >> 5;
    const int lane = tid & 31;
    const int h     = blockIdx.x;
    const int which = blockIdx.z;
    const int m0w = wid * 16;

    const __nv_bfloat16* Wh = g_Whi + (size_t)which * W_ELEMS + (size_t)h * 128 * 128;
    const __nv_bfloat16* Wl = g_Wlo + (size_t)which * W_ELEMS + (size_t)h * 128 * 128;
    __nv_bfloat16* Ohi = (which == 0) ? g_Qhi : (which == 1) ? g_Khi : g_Vhi;
    __nv_bfloat16* Olo = (which == 0) ? g_Qlo : (which == 1) ? g_Klo : g_Vlo;

#pragma unroll
    for (int it = 0; it < 8; it++) {
        int idx = tid + it * 256;
        int r = idx >> 4, s = idx & 15;
        uint32_t o = swz((uint32_t)(r * 256 + s * 16));
        size_t ge = (size_t)r * 128 + s * 8;
        cpa(sb + PWHI + o, Wh + ge);
        cpa(sb + PWLO + o, Wl + ge);
    }
    {
        size_t xoff = (size_t)(blockIdx.y * 4) * 128 * 128;
#pragma unroll
        for (int it = 0; it < 8; it++) {
            int idx = tid + it * 256;
            int r = idx >> 4, s = idx & 15;
            uint32_t o = swz((uint32_t)(r * 256 + s * 16));
            size_t ge = xoff + (size_t)r * 128 + s * 8;
            cpa(sb + PXBUF + PXHI + o, g_xhi + ge);
            cpa(sb + PXBUF + PXLO + o, g_xlo + ge);
        }
    }
    CP_COMMIT();

    const int l15 = lane & 15;
    const int lhi8 = (lane >> 4) << 3;
    const int bl_row = ((lane >> 4) << 3) + (lane & 7);
    const int bl_col = ((lane >> 3) & 1) << 3;
    const float mul = (which == 0) ? SCALE : 1.0f;
    const int g = lane >> 2;
    const int t = lane & 3;

    for (int mt = 0; mt < 4; mt++) {
        const uint32_t xb = sb + PXBUF + (mt & 1) * PXSTRIDE;
        const int m0 = (blockIdx.y * 4 + mt) * 128;

        if (mt + 1 < 4) {
            size_t xoff = (size_t)(m0 + 128) * 128;
#pragma unroll
            for (int it = 0; it < 8; it++) {
                int idx = tid + it * 256;
                int r = idx >> 4, s = idx & 15;
                uint32_t o = swz((uint32_t)(r * 256 + s * 16));
                size_t ge = xoff + (size_t)r * 128 + s * 8;
                uint32_t dst = sb + PXBUF + ((mt + 1) & 1) * PXSTRIDE;
                cpa(dst + PXHI + o, g_xhi + ge);
                cpa(dst + PXLO + o, g_xlo + ge);
            }
            CP_COMMIT();
            CP_WAIT(1);
        } else {
            CP_WAIT(0);
        }
        __syncthreads();

        float acc[16][4];
#pragma unroll
        for (int j = 0; j < 16; j++)
#pragma unroll
            for (int e = 0; e < 4; e++) acc[j][e] = 0.f;

#pragma unroll
        for (int kc = 0; kc < 8; kc++) {
            uint32_t ah[4], al[4];
            {
                uint32_t o = swz((uint32_t)((m0w + l15) * 256 + (kc * 16 + lhi8) * 2));
                ldsm4(xb + PXHI + o, ah);
                ldsm4(xb + PXLO + o, al);
            }
#pragma unroll
            for (int jj = 0; jj < 8; jj++) {
                uint32_t bh4[4], bl4[4];
                uint32_t o = swz((uint32_t)((jj * 16 + bl_row) * 256 + (kc * 16 + bl_col) * 2));
                ldsm4(sb + PWHI + o, bh4);
                ldsm4(sb + PWLO + o, bl4);
                mma16816(acc[2 * jj],     ah, bh4[0], bh4[1]);
                mma16816(acc[2 * jj],     ah, bl4[0], bl4[1]);
                mma16816(acc[2 * jj],     al, bh4[0], bh4[1]);
                mma16816(acc[2 * jj + 1], ah, bh4[2], bh4[3]);
                mma16816(acc[2 * jj + 1], ah, bl4[2], bl4[3]);
                mma16816(acc[2 * jj + 1], al, bh4[2], bh4[3]);
            }
        }

#pragma unroll
        for (int half = 0; half < 2; half++) {
            int m = m0 + m0w + g + half * 8;
            int b = m >> 11;
            int s = m & 2047;
            size_t rbase = (((size_t)(b * Hh + h)) * Ss + s) * Dd;
#pragma unroll
            for (int j = 0; j < 16; j++) {
                float v0 = acc[j][half * 2]     * mul;
                float v1 = acc[j][half * 2 + 1] * mul;
                float h0, l0, h1, l1;
                sp(v0, h0, l0);
                sp(v1, h1, l1);
                size_t off = rbase + j * 8 + 2 * t;
                *reinterpret_cast<uint32_t*>(Ohi + off) = pk(h0, h1);
                *reinterpret_cast<uint32_t*>(Olo + off) = pk(l0, l1);
            }
        }
        __syncthreads();
    }
}

// ===========================================================================
// Kernel 2: persistent tensor-core attention, 128 threads, 2 CTAs/SM.
// Unit = (bh, 64-row q-tile); KV tiles of 32 rows, double-buffered,
// SINGLE syncthreads per tile (prefetch issued after the sync).
// ===========================================================================
#define QHI 0
#define QLO 16384
#define BUF0 32768
#define BUFSTRIDE 32768
#define BKHI 0
#define BKLO 8192
#define BVHI 16384
#define BVLO 24576
#define UNIT_SLOT 98304
#define ATTN_SMEM 98432

__device__ __forceinline__ void prefetch_kv32(uint32_t sb, int buf,
                                              const __nv_bfloat16* Kh, const __nv_bfloat16* Kl,
                                              const __nv_bfloat16* Vh, const __nv_bfloat16* Vl,
                                              int kt, int tid) {
    uint32_t base = sb + BUF0 + buf * BUFSTRIDE;
    size_t goff = (size_t)kt * 32 * 128;
#pragma unroll
    for (int it = 0; it < 4; it++) {
        int idx = tid + it * 128;
        int r = idx >> 4, s = idx & 15;
        uint32_t o = swz((uint32_t)(r * 256 + s * 16));
        size_t ge = goff + (size_t)r * 128 + s * 8;
        cpa(base + BKHI + o, Kh + ge);
        cpa(base + BKLO + o, Kl + ge);
        cpa(base + BVHI + o, Vh + ge);
        cpa(base + BVLO + o, Vl + ge);
    }
}

__global__ __launch_bounds__(128, 2)
void attn_mma(float* __restrict__ out)
{
    extern __shared__ char sm[];
    const uint32_t sb = (uint32_t)__cvta_generic_to_shared(sm);
    volatile int* unit_sh = reinterpret_cast<volatile int*>(sm + UNIT_SLOT);
    const int tid  = threadIdx.x;
    const int wid  = tid >> 5;
    const int lane = tid & 31;
    const int m0w = wid * 16;

    const int l15 = lane & 15;
    const int lhi8 = (lane >> 4) << 3;
    const int bl_row = ((lane >> 4) << 3) + (lane & 7);
    const int bl_col = ((lane >> 3) & 1) << 3;
    const int g = lane >> 2;
    const int t = lane & 3;

    int unit = blockIdx.x;
    while (unit < UNITS) {
        const int bh = unit >> 5;
        const int q0 = (unit & 31) << 6;

        const __nv_bfloat16* Qh = g_Qhi + ((size_t)bh * Ss + q0) * Dd;
        const __nv_bfloat16* Ql = g_Qlo + ((size_t)bh * Ss + q0) * Dd;
        const __nv_bfloat16* Kh = g_Khi + (size_t)bh * Ss * Dd;
        const __nv_bfloat16* Kl = g_Klo + (size_t)bh * Ss * Dd;
        const __nv_bfloat16* Vh = g_Vhi + (size_t)bh * Ss * Dd;
        const __nv_bfloat16* Vl = g_Vlo + (size_t)bh * Ss * Dd;

        // Stage Q (64 x 128 hi/lo) + prefetch KV tile 0 (one group)
#pragma unroll
        for (int it = 0; it < 8; it++) {
            int idx = tid + it * 128;
            int r = idx >> 4, s = idx & 15;
            uint32_t o = swz((uint32_t)(r * 256 + s * 16));
            size_t ge = (size_t)r * 128 + s * 8;
            cpa(sb + QHI + o, Qh + ge);
            cpa(sb + QLO + o, Ql + ge);
        }
        prefetch_kv32(sb, 0, Kh, Kl, Vh, Vl, 0, tid);
        CP_COMMIT();

        float zacc[16][4];
#pragma unroll
        for (int j = 0; j < 16; j++)
#pragma unroll
            for (int e = 0; e < 4; e++) zacc[j][e] = 0.f;

        for (int kt = 0; kt < 64; kt++) {
            const uint32_t kb = sb + BUF0 + (kt & 1) * BUFSTRIDE;

            // tile kt is the only outstanding group; wait + single barrier
            CP_WAIT(0);
            __syncthreads();

            // Issue next tile's loads now: buffer (kt+1)&1 was last read in
            // iteration kt-1, and every warp passed the barrier above.
            if (kt + 1 < 64) {
                prefetch_kv32(sb, (kt + 1) & 1, Kh, Kl, Vh, Vl, kt + 1, tid);
                CP_COMMIT();
            }

            // ---- GEMM1: S[16,32] = Q . K^T ----
            float sacc[4][4];
#pragma unroll
            for (int j = 0; j < 4; j++)
#pragma unroll
                for (int e = 0; e < 4; e++) sacc[j][e] = 0.f;

#pragma unroll
            for (int kc = 0; kc < 8; kc++) {
                uint32_t ah[4], al[4];
                {
                    uint32_t o = swz((uint32_t)((m0w + l15) * 256 + (kc * 16 + lhi8) * 2));
                    ldsm4(sb + QHI + o, ah);
                    ldsm4(sb + QLO + o, al);
                }
#pragma unroll
                for (int jj = 0; jj < 2; jj++) {
                    uint32_t bh4[4], bl4[4];
                    uint32_t o = swz((uint32_t)((jj * 16 + bl_row) * 256 + (kc * 16 + bl_col) * 2));
                    ldsm4(kb + BKHI + o, bh4);
                    ldsm4(kb + BKLO + o, bl4);
                    mma16816(sacc[2 * jj],     ah, bh4[0], bh4[1]);
                    mma16816(sacc[2 * jj],     ah, bl4[0], bl4[1]);
                    mma16816(sacc[2 * jj],     al, bh4[0], bh4[1]);
                    mma16816(sacc[2 * jj + 1], ah, bh4[2], bh4[3]);
                    mma16816(sacc[2 * jj + 1], ah, bl4[2], bl4[3]);
                    mma16816(sacc[2 * jj + 1], al, bh4[2], bh4[3]);
                }
            }

            // ---- GEMM2: Z[16,128] += S . V ----
#pragma unroll
            for (int p = 0; p < 2; p++) {
                uint32_t ah[4], al[4];
                {
                    float h0, l0, h1, l1;
                    sp(sacc[2 * p][0], h0, l0); sp(sacc[2 * p][1], h1, l1);
                    ah[0] = pk(h0, h1); al[0] = pk(l0, l1);
                    sp(sacc[2 * p][2], h0, l0); sp(sacc[2 * p][3], h1, l1);
                    ah[1] = pk(h0, h1); al[1] = pk(l0, l1);
                    sp(sacc[2 * p + 1][0], h0, l0); sp(sacc[2 * p + 1][1], h1, l1);
                    ah[2] = pk(h0, h1); al[2] = pk(l0, l1);
                    sp(sacc[2 * p + 1][2], h0, l0); sp(sacc[2 * p + 1][3], h1, l1);
                    ah[3] = pk(h0, h1); al[3] = pk(l0, l1);
                }
#pragma unroll
                for (int np = 0; np < 8; np++) {
                    uint32_t bh4[4], bl4[4];
                    uint32_t o = swz((uint32_t)((p * 16 + l15) * 256 + (np * 16 + lhi8) * 2));
                    ldsm4t(kb + BVHI + o, bh4);
                    ldsm4t(kb + BVLO + o, bl4);
                    mma16816(zacc[2 * np],     ah, bh4[0], bh4[1]);
                    mma16816(zacc[2 * np],     ah, bl4[0], bl4[1]);
                    mma16816(zacc[2 * np],     al, bh4[0], bh4[1]);
                    mma16816(zacc[2 * np + 1], ah, bh4[2], bh4[3]);
                    mma16816(zacc[2 * np + 1], ah, bl4[2], bl4[3]);
                    mma16816(zacc[2 * np + 1], al, bh4[2], bh4[3]);
                }
            }
        }

        // ---- epilogue: softmax over head dim ----
#pragma unroll
        for (int half = 0; half < 2; half++) {
            float e[32];
#pragma unroll
            for (int j = 0; j < 16; j++) {
                e[2 * j]     = zacc[j][half * 2];
                e[2 * j + 1] = zacc[j][half * 2 + 1];
            }
            float m = e[0];
#pragma unroll
            for (int c = 1; c < 32; c++) m = fmaxf(m, e[c]);
            m = fmaxf(m, __shfl_xor_sync(0xffffffffu, m, 1));
            m = fmaxf(m, __shfl_xor_sync(0xffffffffu, m, 2));

            float ssum = 0.f;
#pragma unroll
            for (int c = 0; c < 32; c++) { e[c] = __expf(e[c] - m); ssum += e[c]; }
            ssum += __shfl_xor_sync(0xffffffffu, ssum, 1);
            ssum += __shfl_xor_sync(0xffffffffu, ssum, 2);
            float inv = 1.0f / ssum;

            int row = q0 + m0w + g + half * 8;
            float* orow = out + ((size_t)bh * Ss + row) * Dd;
#pragma unroll
            for (int j = 0; j < 16; j++) {
                float2 o2 = make_float2(e[2 * j] * inv, e[2 * j + 1] * inv);
                *reinterpret_cast<float2*>(orow + j * 8 + 2 * t) = o2;
            }
        }

        // ---- work stealing: ONE fetch per CTA, broadcast via smem ----
        if (tid == 0) *unit_sh = atomicAdd(&g_ctr, 1);
        __syncthreads();
        unit = *unit_sh;
        // no trailing barrier needed: unit_sh is next written only after all
        // threads pass the 64 barriers of the next unit's mainloop
    }
}

// ===========================================================================

extern "C" void kernel_launch(void* const* d_in, const int* in_sizes, int n_in,
                              void* d_out, int out_size)
{
    (void)in_sizes; (void)n_in; (void)out_size;
    const float* x  = (const float*)d_in[0];
    const float* Wq = (const float*)d_in[1];
    const float* Wk = (const float*)d_in[2];
    const float* Wv = (const float*)d_in[3];
    float* out = (float*)d_out;

    cudaFuncSetAttribute(proj_mma, cudaFuncAttributeMaxDynamicSharedMemorySize, PROJ_SMEM);
    cudaFuncSetAttribute(attn_mma, cudaFuncAttributeMaxDynamicSharedMemorySize, ATTN_SMEM);

    split_all<<<(TOT4 + 255) / 256, 256>>>(x, Wq, Wk, Wv);
    proj_mma<<<dim3(Hh, 16, 3), 256, PROJ_SMEM>>>();
    attn_mma<<<ATTN_GRID, 128, ATTN_SMEM>>>(out);
}